// round 13
// baseline (speedup 1.0000x reference)
#include <cuda_runtime.h>
#include <cuda_bf16.h>
#include <cuda_fp16.h>
#include <math.h>
#include <stdint.h>

typedef unsigned long long ull;

#define B_SZ   64
#define NSTEP  31
#define EMB    300
#define FEAT   4100
#define HID    512
#define G3     1536
#define VOCAB  32000
#define MROWS  1984
#define MPAD   2048
#define GRU_BLOCKS 128

// ---------------- device scratch ----------------
__device__ float g_wihT[EMB * G3];
__device__ float g_xg[MROWS * G3];
__device__ float g_ht[2][HID * B_SZ];       // transposed hidden [j][b]
__device__ __half g_Ah[MPAD * HID];         // fp16(h) rows for classifier
__device__ __half g_Bh[(long)VOCAB * HID];  // fp16(W_cls^T)
__device__ unsigned g_bar_cnt;

// ---------------- helpers ----------------
__device__ __forceinline__ void fma2(ull& d, ull a, ull b) {
    asm("fma.rn.f32x2 %0, %1, %2, %0;" : "+l"(d) : "l"(a), "l"(b));
}
__device__ __forceinline__ ull pack2(float x) {
    ull r; asm("mov.b64 %0, {%1, %2};" : "=l"(r) : "f"(x), "f"(x)); return r;
}
__device__ __forceinline__ void unpack2(ull d, float& lo, float& hi) {
    asm("mov.b64 {%0, %1}, %2;" : "=f"(lo), "=f"(hi) : "l"(d));
}
__device__ __forceinline__ uint32_t s2u(const void* p) {
    uint32_t a;
    asm("{ .reg .u64 t; cvta.to.shared.u64 t, %1; cvt.u32.u64 %0, t; }"
        : "=r"(a) : "l"(p));
    return a;
}
__device__ __forceinline__ uint32_t swz64(uint32_t bo) {
    return bo ^ (((bo >> 7) & 3) << 4);
}
__device__ __forceinline__ ulonglong2 ldcg128(const float* p) {
    ulonglong2 v;
    asm volatile("ld.global.cg.v2.u64 {%0, %1}, [%2];"
                 : "=l"(v.x), "=l"(v.y) : "l"(p));
    return v;
}

// ================= launch 1: weight prep =================
// blocks [0,1800): transpose w_ih -> g_wihT
// blocks [1800,17800): convert W_cls -> g_Bh fp16 [n][k]
// blocks [17800,17816): zero g_Ah tail rows [1984,2048)
#define PREPW_BLOCKS 17816

__global__ void __launch_bounds__(256)
prep_w(const float* __restrict__ w_ih, const float* __restrict__ W_cls) {
    __shared__ float tile[32][33];
    int blk = blockIdx.x;
    int tid = threadIdx.x;
    if (blk == 0 && tid == 0) g_bar_cnt = 0u;   // reset grid barrier per replay

    if (blk < 1800) {
        int idx = blk * 256 + tid;               // < EMB*G3 exactly
        int k = idx / G3, g = idx - k * G3;
        g_wihT[idx] = w_ih[g * EMB + k];
    } else if (blk < 17800) {
        int cb = blk - 1800;
        int n0 = (cb % 1000) * 32, k0 = (cb / 1000) * 32;
        int tx = tid & 31, ty = tid >> 5;        // 32 x 8
#pragma unroll
        for (int j = 0; j < 32; j += 8)
            tile[ty + j][tx] = W_cls[(long)(k0 + ty + j) * VOCAB + n0 + tx];
        __syncthreads();
#pragma unroll
        for (int j = 0; j < 32; j += 8) {
            int n = n0 + ty + j, k = k0 + tx;
            g_Bh[(long)n * HID + k] = __float2half_rn(tile[tx][ty + j]);
        }
    } else {
        int idx = (blk - 17800) * 256 + tid;     // 4096 uint4
        uint4 z = make_uint4(0u, 0u, 0u, 0u);
        *(uint4*)(g_Ah + (long)MROWS * HID + idx * 8) = z;
    }
}

// ================= launch 2: h0 (writes transposed h[j][b]) ===============
__global__ __launch_bounds__(256)
void h0_kernel(const float* __restrict__ vis, const float* __restrict__ tof,
               const float* __restrict__ W_map, const float* __restrict__ b_map,
               float* __restrict__ h_out) {
    __shared__ __align__(16) float fT[64][66];
    __shared__ float ws[64][8];
    __shared__ float red[4][64][8];
    int tid = threadIdx.x;
    int kg = tid >> 6;
    int inner = tid & 63;
    int bg = inner >> 3, b0 = bg * 8;
    int jl = inner & 7;
    int j0 = blockIdx.x * 8;
    int j = j0 + jl;

    ull acc[4] = {0ull, 0ull, 0ull, 0ull};

    for (int kc = 0; kc < FEAT; kc += 64) {
#pragma unroll
        for (int q = 0; q < 16; q++) {
            int id = tid + q * 256;
            int b = id >> 6, kq = id & 63;
            int f = kc + kq;
            float v = 0.f;
            if (f < 2048) v = vis[b * 2048 + f];
            else if (f < FEAT) v = tof[b * 2052 + (f - 2048)];
            fT[kq][b] = v;
        }
#pragma unroll
        for (int q = 0; q < 2; q++) {
            int id = tid + q * 256;
            int k = id >> 3, jj = id & 7;
            int f = kc + k;
            ws[k][jj] = (f < FEAT) ? W_map[f * HID + j0 + jj] : 0.f;
        }
        __syncthreads();
        int kbase = kg * 16;
#pragma unroll
        for (int i = 0; i < 16; i++) {
            int k = kbase + i;
            ull w2 = pack2(ws[k][jl]);
#pragma unroll
            for (int p = 0; p < 4; p++) {
                ull hp = *(const ull*)&fT[k][b0 + 2 * p];
                fma2(acc[p], w2, hp);
            }
        }
        __syncthreads();
    }
#pragma unroll
    for (int p = 0; p < 4; p++) {
        float lo, hi; unpack2(acc[p], lo, hi);
        red[kg][inner][2 * p] = lo; red[kg][inner][2 * p + 1] = hi;
    }
    __syncthreads();
    if (kg == 0) {
        for (int bi = 0; bi < 8; bi++) {
            int b = b0 + bi;
            float s = 0.f;
#pragma unroll
            for (int g = 0; g < 4; g++) s += red[g][inner][bi];
            s += b_map[j];
            h_out[j * B_SZ + b] = fmaxf(s, 0.f);
        }
    }
}

// ================= launch 3: x_gates fp32 GEMM =================
__global__ __launch_bounds__(256)
void gemm128(const float* __restrict__ A, const float* __restrict__ Bm,
             const float* __restrict__ bias, float* __restrict__ C,
             int M, int N, int K) {
    __shared__ __align__(16) float As[16][132];
    __shared__ __align__(16) float Bs[16][128];
    int tid = threadIdx.x;
    int mtile = blockIdx.y * 128;
    int ntile = blockIdx.x * 128;
    int tm = tid >> 4, tn = tid & 15;
    int m0 = tm * 8, n0 = tn * 8;

    ull acc[8][4];
#pragma unroll
    for (int i = 0; i < 8; i++)
#pragma unroll
        for (int j = 0; j < 4; j++) acc[i][j] = 0ull;

    int nchunks = (K + 15) >> 4;
    for (int c = 0; c < nchunks; c++) {
        int kc = c << 4;
#pragma unroll
        for (int q = 0; q < 2; q++) {
            int id = tid * 2 + q;
            int row = id >> 2;
            int kq = (id & 3) * 4;
            int m = mtile + row;
            float4 v = make_float4(0.f, 0.f, 0.f, 0.f);
            if (m < M) {
                int bb = m / 31, tt = m - bb * 31;
                long roff = (long)(bb * 32 + tt) * K;
                int k = kc + kq;
                if (k + 3 < K) v = *(const float4*)(A + roff + k);
                else {
                    float tmp[4] = {0.f, 0.f, 0.f, 0.f};
#pragma unroll
                    for (int u = 0; u < 4; u++)
                        if (k + u < K) tmp[u] = A[roff + k + u];
                    v = make_float4(tmp[0], tmp[1], tmp[2], tmp[3]);
                }
            }
            As[kq + 0][row] = v.x; As[kq + 1][row] = v.y;
            As[kq + 2][row] = v.z; As[kq + 3][row] = v.w;
        }
#pragma unroll
        for (int q = 0; q < 2; q++) {
            int id = tid + q * 256;
            int r = id >> 5;
            int nq = (id & 31) * 4;
            int k = kc + r;
            float4 v = make_float4(0.f, 0.f, 0.f, 0.f);
            if (k < K) v = *(const float4*)(Bm + (long)k * N + ntile + nq);
            *(float4*)&Bs[r][nq] = v;
        }
        __syncthreads();
#pragma unroll
        for (int kk = 0; kk < 16; kk++) {
            float4 a0 = *(const float4*)&As[kk][m0];
            float4 a1 = *(const float4*)&As[kk][m0 + 4];
            const ull* bp = (const ull*)&Bs[kk][n0];
            ull b2[4] = {bp[0], bp[1], bp[2], bp[3]};
            float av[8] = {a0.x, a0.y, a0.z, a0.w, a1.x, a1.y, a1.z, a1.w};
#pragma unroll
            for (int i = 0; i < 8; i++) {
                ull ai = pack2(av[i]);
#pragma unroll
                for (int j = 0; j < 4; j++) fma2(acc[i][j], ai, b2[j]);
            }
        }
        __syncthreads();
    }
    float bvals[8];
#pragma unroll
    for (int j = 0; j < 8; j++) bvals[j] = bias[ntile + n0 + j];
#pragma unroll
    for (int i = 0; i < 8; i++) {
        int m = mtile + m0 + i;
        if (m < M) {
            float* crow = C + (long)m * N + ntile + n0;
#pragma unroll
            for (int j = 0; j < 4; j++) {
                float lo, hi; unpack2(acc[i][j], lo, hi);
                crow[2 * j]     = lo + bvals[2 * j];
                crow[2 * j + 1] = hi + bvals[2 * j + 1];
            }
        }
    }
}

// ================= launch 4 (profiled): persistent GRU v3 =================
// 128 CTAs x 256 threads (round-11 measured config) + stage-2 input prefetch.
// Weights in smem once; h via L2 .cg; grid barrier per step; writes fp16 Ah.
#define WTP 16
#define GRU_SMEM ((HID * WTP + 16 * 16 * 48) * 4)   // 32KB w + 48KB part

__global__ void __launch_bounds__(256)
gru_persist3(const float* __restrict__ w_hh, const float* __restrict__ b_hh) {
    extern __shared__ float sm[];
    float* w_t = sm;                        // [512][16]
    float* part = w_t + HID * WTP;          // [16 ks][16 tile][48]
    int tid = threadIdx.x;
    int j0 = blockIdx.x * 4;

    // weights once
#pragma unroll
    for (int q = 0; q < 6; q++) {
        int id = tid + q * 256;
        int r = id % 12, k4 = id / 12;
        int grow = (r >> 2) * HID + j0 + (r & 3);
        int pos = (r < 6) ? r : r + 2;
        float4 v = *(const float4*)(w_hh + (long)grow * HID + k4 * 4);
        w_t[(k4 * 4 + 0) * WTP + pos] = v.x;
        w_t[(k4 * 4 + 1) * WTP + pos] = v.y;
        w_t[(k4 * 4 + 2) * WTP + pos] = v.z;
        w_t[(k4 * 4 + 3) * WTP + pos] = v.w;
    }

    // stage-1 roles
    int ks = tid >> 4;
    int tile = tid & 15;
    int bg = tile >> 1, gcg = tile & 1;
    int b0 = bg * 8, gbase = gcg * 8;
    int kbase = ks * 32;
    // stage-2 roles
    int b = tid & 63, jg = tid >> 6;
    int bgr = b >> 3, bi = b & 7;
    int tR = bgr * 2 + 0, iR = jg * 8 + bi;
    int tZ, iZ;
    if (jg < 2) { tZ = bgr * 2 + 0; iZ = (4 + jg) * 8 + bi; }
    else        { tZ = bgr * 2 + 1; iZ = (jg - 2) * 8 + bi; }
    int tN = bgr * 2 + 1, iN = (2 + jg) * 8 + bi;
    int j = j0 + jg;
    float bhr = b_hh[j], bhz = b_hh[HID + j], bhn = b_hh[2 * HID + j];
    __syncthreads();

    for (int t = 0; t < NSTEP; t++) {
        const float* h_in = g_ht[t & 1];
        float* h_out = g_ht[(t + 1) & 1];

        // ---- prefetch stage-2 inputs NOW (overlap with stage-1 compute) ----
        const float* xrow = g_xg + ((long)b * NSTEP + t) * G3;
        float xr = __ldcg(xrow + j);
        float xz = __ldcg(xrow + HID + j);
        float xn = __ldcg(xrow + 2 * HID + j);
        float hp = __ldcg(h_in + j * B_SZ + b);

        ull acc[4][6];
#pragma unroll
        for (int p = 0; p < 4; p++)
#pragma unroll
            for (int g = 0; g < 6; g++) acc[p][g] = 0ull;

#pragma unroll 8
        for (int kk = 0; kk < 32; kk++) {
            int k = kbase + kk;
            const float* hr = h_in + k * B_SZ + b0;
            ulonglong2 ha = ldcg128(hr);
            ulonglong2 hb = ldcg128(hr + 4);
            ull h2[4] = {ha.x, ha.y, hb.x, hb.y};
            float4 w0 = *(const float4*)(w_t + k * WTP + gbase);
            float4 w1 = *(const float4*)(w_t + k * WTP + gbase + 4);
            float wv[6] = {w0.x, w0.y, w0.z, w0.w, w1.x, w1.y};
#pragma unroll
            for (int g = 0; g < 6; g++) {
                ull wp = pack2(wv[g]);
#pragma unroll
                for (int p = 0; p < 4; p++) fma2(acc[p][g], wp, h2[p]);
            }
        }
        float* pb = part + (ks * 16 + tile) * 48;
#pragma unroll
        for (int g = 0; g < 6; g++) {
            float l0, h0v, l1, h1, l2, h2v, l3, h3;
            unpack2(acc[0][g], l0, h0v); unpack2(acc[1][g], l1, h1);
            unpack2(acc[2][g], l2, h2v); unpack2(acc[3][g], l3, h3);
            *(float4*)(pb + g * 8)     = make_float4(l0, h0v, l1, h1);
            *(float4*)(pb + g * 8 + 4) = make_float4(l2, h2v, l3, h3);
        }
        __syncthreads();

        float sr = 0.f, sz = 0.f, sn = 0.f;
#pragma unroll
        for (int s = 0; s < 16; s++) {
            sr += part[(s * 16 + tR) * 48 + iR];
            sz += part[(s * 16 + tZ) * 48 + iZ];
            sn += part[(s * 16 + tN) * 48 + iN];
        }
        sr += bhr; sz += bhz; sn += bhn;
        float r_ = 1.f / (1.f + expf(-(xr + sr)));
        float z_ = 1.f / (1.f + expf(-(xz + sz)));
        float n_ = tanhf(xn + r_ * sn);
        float hn = (1.f - z_) * n_ + z_ * hp;
        h_out[j * B_SZ + b] = hn;
        g_Ah[((long)b * NSTEP + t) * HID + j] = __float2half_rn(hn);

        if (t < NSTEP - 1) {
            __threadfence();
            __syncthreads();
            if (tid == 0) {
                atomicAdd(&g_bar_cnt, 1u);
                unsigned target = (unsigned)GRU_BLOCKS * (unsigned)(t + 1);
                while (*(volatile unsigned*)&g_bar_cnt < target) { }
                __threadfence();
            }
            __syncthreads();
        }
    }
}

// ================= launch 5: classifier (unchanged, 255us measured) ======
#define CLS_SMEM 32768
#define BUF_STRIDE 16384

__global__ void __launch_bounds__(256)
cls_mma6(const float* __restrict__ bias, float* __restrict__ out) {
    extern __shared__ char csm[];
    uint32_t sb = s2u(csm);
    int tid = threadIdx.x;
    int wid = tid >> 5, l = tid & 31;
    int wm = wid >> 2, wn = wid & 3;
    int mtile = blockIdx.x * 128;
    int ntile = blockIdx.y * 128;

    float d[4][4][4];
#pragma unroll
    for (int i = 0; i < 4; i++)
#pragma unroll
        for (int j = 0; j < 4; j++)
#pragma unroll
            for (int k = 0; k < 4; k++) d[i][j][k] = 0.f;

    int rA = l & 15, cA = (l >> 4) * 16;
    int rB = l & 7,  cB = ((l >> 3) & 1) * 16;

#define PREFETCH6(c)                                                           \
    do {                                                                       \
        int kc_ = (c) * 32;                                                    \
        uint32_t bufb_ = sb + ((c) & 1) * BUF_STRIDE;                          \
        _Pragma("unroll")                                                      \
        for (int q = 0; q < 4; q++) {                                          \
            int id = tid + q * 256;                                            \
            int seg = id >> 9;                                                 \
            int r = (id >> 2) & 127;                                           \
            int g16 = id & 3;                                                  \
            const __half* src = (seg == 0)                                     \
                ? g_Ah + (long)(mtile + r) * HID                               \
                : g_Bh + (long)(ntile + r) * HID;                              \
            uint32_t dst = bufb_ + seg * 8192 +                                \
                           swz64((uint32_t)(r * 64 + g16 * 16));               \
            asm volatile("cp.async.ca.shared.global [%0], [%1], 16;"           \
                         :: "r"(dst), "l"(src + kc_ + g16 * 8) : "memory");    \
        }                                                                      \
        asm volatile("cp.async.commit_group;" ::: "memory");                   \
    } while (0)

    PREFETCH6(0);
    for (int c = 0; c < 16; c++) {
        if (c < 15) {
            PREFETCH6(c + 1);
            asm volatile("cp.async.wait_group 1;" ::: "memory");
        } else {
            asm volatile("cp.async.wait_group 0;" ::: "memory");
        }
        __syncthreads();
        uint32_t bufb = sb + (c & 1) * BUF_STRIDE;

#pragma unroll
        for (int kst = 0; kst < 2; kst++) {
            uint32_t bh[4][2];
#pragma unroll
            for (int nt = 0; nt < 4; nt++) {
                int row = wn * 32 + nt * 8 + rB;
                uint32_t off = swz64((uint32_t)(row * 64 + kst * 32 + cB));
                asm volatile(
                    "ldmatrix.sync.aligned.m8n8.x2.shared.b16 {%0,%1}, [%2];"
                    : "=r"(bh[nt][0]), "=r"(bh[nt][1])
                    : "r"(bufb + 8192 + off));
            }
#pragma unroll
            for (int mt = 0; mt < 4; mt++) {
                int row = wm * 64 + mt * 16 + rA;
                uint32_t off = swz64((uint32_t)(row * 64 + kst * 32 + cA));
                uint32_t ah[4];
                asm volatile(
                    "ldmatrix.sync.aligned.m8n8.x4.shared.b16 {%0,%1,%2,%3}, [%4];"
                    : "=r"(ah[0]), "=r"(ah[1]), "=r"(ah[2]), "=r"(ah[3])
                    : "r"(bufb + off));
#pragma unroll
                for (int nt = 0; nt < 4; nt++) {
                    asm volatile(
                        "mma.sync.aligned.m16n8k16.row.col.f32.f16.f16.f32 "
                        "{%0,%1,%2,%3}, {%4,%5,%6,%7}, {%8,%9}, {%0,%1,%2,%3};"
                        : "+f"(d[mt][nt][0]), "+f"(d[mt][nt][1]),
                          "+f"(d[mt][nt][2]), "+f"(d[mt][nt][3])
                        : "r"(ah[0]), "r"(ah[1]), "r"(ah[2]), "r"(ah[3]),
                          "r"(bh[nt][0]), "r"(bh[nt][1]));
                }
            }
        }
        __syncthreads();
    }

    int rbase = mtile + wm * 64 + (l >> 2);
    int cbase = ntile + wn * 32 + (l & 3) * 2;
#pragma unroll
    for (int nt = 0; nt < 4; nt++) {
        int col = cbase + nt * 8;
        float b0 = bias[col], b1 = bias[col + 1];
#pragma unroll
        for (int mt = 0; mt < 4; mt++) {
            int r0 = rbase + mt * 16;
            if (r0 < MROWS) {
                float2 v = make_float2(d[mt][nt][0] + b0, d[mt][nt][1] + b1);
                *(float2*)(out + (long)r0 * VOCAB + col) = v;
            }
            if (r0 + 8 < MROWS) {
                float2 v = make_float2(d[mt][nt][2] + b0, d[mt][nt][3] + b1);
                *(float2*)(out + (long)(r0 + 8) * VOCAB + col) = v;
            }
        }
    }
}

// ---------------- launch ----------------
extern "C" void kernel_launch(void* const* d_in, const int* in_sizes, int n_in,
                              void* d_out, int out_size) {
    const float* word_embs = (const float*)d_in[0];
    const float* vis       = (const float*)d_in[1];
    const float* tof       = (const float*)d_in[2];
    const float* W_map     = (const float*)d_in[4];
    const float* b_map     = (const float*)d_in[5];
    const float* w_ih      = (const float*)d_in[6];
    const float* w_hh      = (const float*)d_in[7];
    const float* b_ih      = (const float*)d_in[8];
    const float* b_hh      = (const float*)d_in[9];
    const float* W_cls     = (const float*)d_in[10];
    const float* b_cls     = (const float*)d_in[11];
    float* out = (float*)d_out;

    float *wihT, *xg, *ht;
    cudaGetSymbolAddress((void**)&wihT, g_wihT);
    cudaGetSymbolAddress((void**)&xg,   g_xg);
    cudaGetSymbolAddress((void**)&ht,   g_ht);

    cudaFuncSetAttribute(gru_persist3, cudaFuncAttributeMaxDynamicSharedMemorySize,
                         GRU_SMEM);
    cudaFuncSetAttribute(cls_mma6, cudaFuncAttributeMaxDynamicSharedMemorySize,
                         CLS_SMEM);

    // 1: weight prep (w_ih transpose + W_cls fp16 + Ah tail zero + bar reset)
    prep_w<<<PREPW_BLOCKS, 256>>>(w_ih, W_cls);
    // 2: h0
    h0_kernel<<<64, 256>>>(vis, tof, W_map, b_map, ht);
    // 3: x_gates
    {
        dim3 grid(G3 / 128, (MROWS + 127) / 128);
        gemm128<<<grid, 256>>>(word_embs, wihT, b_ih, xg, MROWS, G3, EMB);
    }
    // 4: persistent GRU  <-- ncu profiled slot
    gru_persist3<<<GRU_BLOCKS, 256, GRU_SMEM>>>(w_hh, b_hh);
    // 5: classifier
    {
        dim3 grid(MPAD / 128, VOCAB / 128);
        cls_mma6<<<grid, 256, CLS_SMEM>>>(b_cls, out);
    }
    (void)in_sizes; (void)n_in; (void)out_size;
}

// round 14
// speedup vs baseline: 1.1399x; 1.1399x over previous
#include <cuda_runtime.h>
#include <cuda_bf16.h>
#include <cuda_fp16.h>
#include <math.h>
#include <stdint.h>

typedef unsigned long long ull;

#define B_SZ   64
#define NSTEP  31
#define EMB    300
#define FEAT   4100
#define HID    512
#define G3     1536
#define VOCAB  32000
#define MROWS  1984
#define MPAD   2048
#define GRU_BLOCKS 128

// ---------------- device scratch ----------------
__device__ float g_wihT[EMB * G3];
__device__ float g_xg[MROWS * G3];
__device__ float g_ht[2][HID * B_SZ];       // transposed hidden [j][b]
__device__ __half g_Ah[MPAD * HID];         // fp16(h) rows for classifier
__device__ __half g_Bh[(long)VOCAB * HID];  // fp16(W_cls^T)
__device__ unsigned g_bar_cnt;

// ---------------- helpers ----------------
__device__ __forceinline__ void fma2(ull& d, ull a, ull b) {
    asm("fma.rn.f32x2 %0, %1, %2, %0;" : "+l"(d) : "l"(a), "l"(b));
}
__device__ __forceinline__ ull pack2(float x) {
    ull r; asm("mov.b64 %0, {%1, %2};" : "=l"(r) : "f"(x), "f"(x)); return r;
}
__device__ __forceinline__ void unpack2(ull d, float& lo, float& hi) {
    asm("mov.b64 {%0, %1}, %2;" : "=f"(lo), "=f"(hi) : "l"(d));
}
__device__ __forceinline__ uint32_t s2u(const void* p) {
    uint32_t a;
    asm("{ .reg .u64 t; cvta.to.shared.u64 t, %1; cvt.u32.u64 %0, t; }"
        : "=r"(a) : "l"(p));
    return a;
}
__device__ __forceinline__ uint32_t swz64(uint32_t bo) {
    return bo ^ (((bo >> 7) & 3) << 4);
}
__device__ __forceinline__ ulonglong2 ldcg128(const float* p) {
    ulonglong2 v;
    asm volatile("ld.global.cg.v2.u64 {%0, %1}, [%2];"
                 : "=l"(v.x), "=l"(v.y) : "l"(p));
    return v;
}

// ================= launch 1: fused prep (round-12, measured-good) ========
// blocks [0,1800): transpose w_ih; [1800,17800): W_cls->fp16;
// [17800,17864): h0; [17864,17880): zero g_Ah tail.
#define PREP_BLOCKS 17880

__global__ void __launch_bounds__(256)
prep(const float* __restrict__ w_ih, const float* __restrict__ W_cls,
     const float* __restrict__ vis, const float* __restrict__ tof,
     const float* __restrict__ W_map, const float* __restrict__ b_map,
     float* __restrict__ h_out) {
    __shared__ float psm[6800];
    int blk = blockIdx.x;
    int tid = threadIdx.x;
    if (blk == 0 && tid == 0) g_bar_cnt = 0u;

    if (blk < 1800) {
        int idx = blk * 256 + tid;
        int k = idx / G3, g = idx - k * G3;
        g_wihT[idx] = w_ih[g * EMB + k];
    } else if (blk < 17800) {
        int cb = blk - 1800;
        int n0 = (cb % 1000) * 32, k0 = (cb / 1000) * 32;
        int tx = tid & 31, ty = tid >> 5;
        float* tile = psm;
#pragma unroll
        for (int j = 0; j < 32; j += 8)
            tile[(ty + j) * 33 + tx] = W_cls[(long)(k0 + ty + j) * VOCAB + n0 + tx];
        __syncthreads();
#pragma unroll
        for (int j = 0; j < 32; j += 8) {
            int n = n0 + ty + j, k = k0 + tx;
            g_Bh[(long)n * HID + k] = __float2half_rn(tile[tx * 33 + ty + j]);
        }
    } else if (blk < 17864) {
        float* fT = psm;
        float* ws = fT + 64 * 66;
        float* red = ws + 64 * 8;
        int kg = tid >> 6;
        int inner = tid & 63;
        int bg = inner >> 3, b0 = bg * 8;
        int jl = inner & 7;
        int j0 = (blk - 17800) * 8;
        int j = j0 + jl;

        ull acc[4] = {0ull, 0ull, 0ull, 0ull};
        for (int kc = 0; kc < FEAT; kc += 64) {
#pragma unroll
            for (int q = 0; q < 16; q++) {
                int id = tid + q * 256;
                int b = id >> 6, kq = id & 63;
                int f = kc + kq;
                float v = 0.f;
                if (f < 2048) v = vis[b * 2048 + f];
                else if (f < FEAT) v = tof[b * 2052 + (f - 2048)];
                fT[kq * 66 + b] = v;
            }
#pragma unroll
            for (int q = 0; q < 2; q++) {
                int id = tid + q * 256;
                int k = id >> 3, jj = id & 7;
                int f = kc + k;
                ws[k * 8 + jj] = (f < FEAT) ? W_map[f * HID + j0 + jj] : 0.f;
            }
            __syncthreads();
            int kbase = kg * 16;
#pragma unroll
            for (int i = 0; i < 16; i++) {
                int k = kbase + i;
                ull w2 = pack2(ws[k * 8 + jl]);
#pragma unroll
                for (int p = 0; p < 4; p++) {
                    ull hp = *(const ull*)(fT + k * 66 + b0 + 2 * p);
                    fma2(acc[p], w2, hp);
                }
            }
            __syncthreads();
        }
#pragma unroll
        for (int p = 0; p < 4; p++) {
            float lo, hi; unpack2(acc[p], lo, hi);
            red[kg * 512 + inner * 8 + 2 * p] = lo;
            red[kg * 512 + inner * 8 + 2 * p + 1] = hi;
        }
        __syncthreads();
        if (kg == 0) {
            for (int bi = 0; bi < 8; bi++) {
                int b = b0 + bi;
                float s = 0.f;
#pragma unroll
                for (int g = 0; g < 4; g++) s += red[g * 512 + inner * 8 + bi];
                s += b_map[j];
                h_out[j * B_SZ + b] = fmaxf(s, 0.f);
            }
        }
    } else {
        int idx = (blk - 17864) * 256 + tid;
        uint4 z = make_uint4(0u, 0u, 0u, 0u);
        *(uint4*)(g_Ah + (long)MROWS * HID + idx * 8) = z;
    }
}

// ================= launch 2: x_gates fp32 GEMM =================
__global__ __launch_bounds__(256)
void gemm128(const float* __restrict__ A, const float* __restrict__ Bm,
             const float* __restrict__ bias, float* __restrict__ C,
             int M, int N, int K) {
    __shared__ __align__(16) float As[16][132];
    __shared__ __align__(16) float Bs[16][128];
    int tid = threadIdx.x;
    int mtile = blockIdx.y * 128;
    int ntile = blockIdx.x * 128;
    int tm = tid >> 4, tn = tid & 15;
    int m0 = tm * 8, n0 = tn * 8;

    ull acc[8][4];
#pragma unroll
    for (int i = 0; i < 8; i++)
#pragma unroll
        for (int j = 0; j < 4; j++) acc[i][j] = 0ull;

    int nchunks = (K + 15) >> 4;
    for (int c = 0; c < nchunks; c++) {
        int kc = c << 4;
#pragma unroll
        for (int q = 0; q < 2; q++) {
            int id = tid * 2 + q;
            int row = id >> 2;
            int kq = (id & 3) * 4;
            int m = mtile + row;
            float4 v = make_float4(0.f, 0.f, 0.f, 0.f);
            if (m < M) {
                int bb = m / 31, tt = m - bb * 31;
                long roff = (long)(bb * 32 + tt) * K;
                int k = kc + kq;
                if (k + 3 < K) v = *(const float4*)(A + roff + k);
                else {
                    float tmp[4] = {0.f, 0.f, 0.f, 0.f};
#pragma unroll
                    for (int u = 0; u < 4; u++)
                        if (k + u < K) tmp[u] = A[roff + k + u];
                    v = make_float4(tmp[0], tmp[1], tmp[2], tmp[3]);
                }
            }
            As[kq + 0][row] = v.x; As[kq + 1][row] = v.y;
            As[kq + 2][row] = v.z; As[kq + 3][row] = v.w;
        }
#pragma unroll
        for (int q = 0; q < 2; q++) {
            int id = tid + q * 256;
            int r = id >> 5;
            int nq = (id & 31) * 4;
            int k = kc + r;
            float4 v = make_float4(0.f, 0.f, 0.f, 0.f);
            if (k < K) v = *(const float4*)(Bm + (long)k * N + ntile + nq);
            *(float4*)&Bs[r][nq] = v;
        }
        __syncthreads();
#pragma unroll
        for (int kk = 0; kk < 16; kk++) {
            float4 a0 = *(const float4*)&As[kk][m0];
            float4 a1 = *(const float4*)&As[kk][m0 + 4];
            const ull* bp = (const ull*)&Bs[kk][n0];
            ull b2[4] = {bp[0], bp[1], bp[2], bp[3]};
            float av[8] = {a0.x, a0.y, a0.z, a0.w, a1.x, a1.y, a1.z, a1.w};
#pragma unroll
            for (int i = 0; i < 8; i++) {
                ull ai = pack2(av[i]);
#pragma unroll
                for (int j = 0; j < 4; j++) fma2(acc[i][j], ai, b2[j]);
            }
        }
        __syncthreads();
    }
    float bvals[8];
#pragma unroll
    for (int j = 0; j < 8; j++) bvals[j] = bias[ntile + n0 + j];
#pragma unroll
    for (int i = 0; i < 8; i++) {
        int m = mtile + m0 + i;
        if (m < M) {
            float* crow = C + (long)m * N + ntile + n0;
#pragma unroll
            for (int j = 0; j < 4; j++) {
                float lo, hi; unpack2(acc[i][j], lo, hi);
                crow[2 * j]     = lo + bvals[2 * j];
                crow[2 * j + 1] = hi + bvals[2 * j + 1];
            }
        }
    }
}

// ================= launch 3: persistent GRU v5 =================
// 128 CTAs x 512 threads (round-12 best config) with:
//  - partials stride 52 (was 48): STS 16-way -> 4-way, LDS conflict-free
//  - stage-2 split across all 512 threads (two 16-deep half sums + combine)
//  - stage-2 input prefetch at step top
#define WTP 16
#define PSTR 52
#define GRU_SMEM ((HID * WTP + 32 * 16 * PSTR + 1024) * 4)

__global__ void __launch_bounds__(512)
gru_persist5(const float* __restrict__ w_hh, const float* __restrict__ b_hh) {
    extern __shared__ float sm[];
    float* w_t = sm;                         // [512][16]
    float* part = w_t + HID * WTP;           // [32 ks][16 tile][52]
    float* red2 = part + 32 * 16 * PSTR;     // [256][3] (padded to 1024)
    int tid = threadIdx.x;
    int j0 = blockIdx.x * 4;

    // weights once: 1536 float4 over 512 threads
#pragma unroll
    for (int q = 0; q < 3; q++) {
        int id = tid + q * 512;
        int r = id % 12, k4 = id / 12;
        int grow = (r >> 2) * HID + j0 + (r & 3);
        int pos = (r < 6) ? r : r + 2;
        float4 v = *(const float4*)(w_hh + (long)grow * HID + k4 * 4);
        w_t[(k4 * 4 + 0) * WTP + pos] = v.x;
        w_t[(k4 * 4 + 1) * WTP + pos] = v.y;
        w_t[(k4 * 4 + 2) * WTP + pos] = v.z;
        w_t[(k4 * 4 + 3) * WTP + pos] = v.w;
    }

    // stage-1 roles: 32 k-slices x 16 tiles
    int ks = tid >> 4;                 // 0..31
    int tile = tid & 15;
    int bg = tile >> 1, gcg = tile & 1;
    int b0 = bg * 8, gbase = gcg * 8;
    int kbase = ks * 16;
    // stage-2 roles: half = tid>>8, (b, jg) from tid&255
    int half = tid >> 8;
    int r2 = tid & 255;
    int b = r2 & 63, jg = r2 >> 6;
    int bgr = b >> 3, bi = b & 7;
    int tR = bgr * 2 + 0, iR = jg * 8 + bi;
    int tZ, iZ;
    if (jg < 2) { tZ = bgr * 2 + 0; iZ = (4 + jg) * 8 + bi; }
    else        { tZ = bgr * 2 + 1; iZ = (jg - 2) * 8 + bi; }
    int tN = bgr * 2 + 1, iN = (2 + jg) * 8 + bi;
    int j = j0 + jg;
    float bhr = b_hh[j], bhz = b_hh[HID + j], bhn = b_hh[2 * HID + j];
    int sbase = half * 16;
    __syncthreads();

    for (int t = 0; t < NSTEP; t++) {
        const float* h_in = g_ht[t & 1];
        float* h_out = g_ht[(t + 1) & 1];

        // prefetch stage-2 inputs (overlap with stage-1)
        float xr = 0.f, xz = 0.f, xn = 0.f, hp = 0.f;
        if (half == 0) {
            const float* xrow = g_xg + ((long)b * NSTEP + t) * G3;
            xr = __ldcg(xrow + j);
            xz = __ldcg(xrow + HID + j);
            xn = __ldcg(xrow + 2 * HID + j);
            hp = __ldcg(h_in + j * B_SZ + b);
        }

        ull acc[4][6];
#pragma unroll
        for (int p = 0; p < 4; p++)
#pragma unroll
            for (int g = 0; g < 6; g++) acc[p][g] = 0ull;

#pragma unroll 8
        for (int kk = 0; kk < 16; kk++) {
            int k = kbase + kk;
            const float* hr = h_in + k * B_SZ + b0;
            ulonglong2 ha = ldcg128(hr);
            ulonglong2 hb = ldcg128(hr + 4);
            ull h2[4] = {ha.x, ha.y, hb.x, hb.y};
            float4 w0 = *(const float4*)(w_t + k * WTP + gbase);
            float4 w1 = *(const float4*)(w_t + k * WTP + gbase + 4);
            float wv[6] = {w0.x, w0.y, w0.z, w0.w, w1.x, w1.y};
#pragma unroll
            for (int g = 0; g < 6; g++) {
                ull wp = pack2(wv[g]);
#pragma unroll
                for (int p = 0; p < 4; p++) fma2(acc[p][g], wp, h2[p]);
            }
        }
        float* pb = part + (ks * 16 + tile) * PSTR;
#pragma unroll
        for (int g = 0; g < 6; g++) {
            float l0, h0v, l1, h1, l2, h2v, l3, h3;
            unpack2(acc[0][g], l0, h0v); unpack2(acc[1][g], l1, h1);
            unpack2(acc[2][g], l2, h2v); unpack2(acc[3][g], l3, h3);
            *(float4*)(pb + g * 8)     = make_float4(l0, h0v, l1, h1);
            *(float4*)(pb + g * 8 + 4) = make_float4(l2, h2v, l3, h3);
        }
        __syncthreads();

        // half-sums over 16 slices each
        float sr = 0.f, sz = 0.f, sn = 0.f;
#pragma unroll
        for (int si = 0; si < 16; si++) {
            int s = sbase + si;
            sr += part[(s * 16 + tR) * PSTR + iR];
            sz += part[(s * 16 + tZ) * PSTR + iZ];
            sn += part[(s * 16 + tN) * PSTR + iN];
        }
        if (half == 1) {
            red2[r2 * 4 + 0] = sr;
            red2[r2 * 4 + 1] = sz;
            red2[r2 * 4 + 2] = sn;
        }
        __syncthreads();

        if (half == 0) {
            sr += red2[r2 * 4 + 0] + bhr;
            sz += red2[r2 * 4 + 1] + bhz;
            sn += red2[r2 * 4 + 2] + bhn;
            float r_ = 1.f / (1.f + expf(-(xr + sr)));
            float z_ = 1.f / (1.f + expf(-(xz + sz)));
            float n_ = tanhf(xn + r_ * sn);
            float hn = (1.f - z_) * n_ + z_ * hp;
            h_out[j * B_SZ + b] = hn;
            g_Ah[((long)b * NSTEP + t) * HID + j] = __float2half_rn(hn);
        }

        if (t < NSTEP - 1) {
            __threadfence();
            __syncthreads();
            if (tid == 0) {
                atomicAdd(&g_bar_cnt, 1u);
                unsigned target = (unsigned)GRU_BLOCKS * (unsigned)(t + 1);
                while (*(volatile unsigned*)&g_bar_cnt < target) { }
                __threadfence();
            }
            __syncthreads();
        }
    }
}

// ================= launch 4: classifier (unchanged, 255us measured) ======
#define CLS_SMEM 32768
#define BUF_STRIDE 16384

__global__ void __launch_bounds__(256)
cls_mma6(const float* __restrict__ bias, float* __restrict__ out) {
    extern __shared__ char csm[];
    uint32_t sb = s2u(csm);
    int tid = threadIdx.x;
    int wid = tid >> 5, l = tid & 31;
    int wm = wid >> 2, wn = wid & 3;
    int mtile = blockIdx.x * 128;
    int ntile = blockIdx.y * 128;

    float d[4][4][4];
#pragma unroll
    for (int i = 0; i < 4; i++)
#pragma unroll
        for (int j = 0; j < 4; j++)
#pragma unroll
            for (int k = 0; k < 4; k++) d[i][j][k] = 0.f;

    int rA = l & 15, cA = (l >> 4) * 16;
    int rB = l & 7,  cB = ((l >> 3) & 1) * 16;

#define PREFETCH6(c)                                                           \
    do {                                                                       \
        int kc_ = (c) * 32;                                                    \
        uint32_t bufb_ = sb + ((c) & 1) * BUF_STRIDE;                          \
        _Pragma("unroll")                                                      \
        for (int q = 0; q < 4; q++) {                                          \
            int id = tid + q * 256;                                            \
            int seg = id >> 9;                                                 \
            int r = (id >> 2) & 127;                                           \
            int g16 = id & 3;                                                  \
            const __half* src = (seg == 0)                                     \
                ? g_Ah + (long)(mtile + r) * HID                               \
                : g_Bh + (long)(ntile + r) * HID;                              \
            uint32_t dst = bufb_ + seg * 8192 +                                \
                           swz64((uint32_t)(r * 64 + g16 * 16));               \
            asm volatile("cp.async.ca.shared.global [%0], [%1], 16;"           \
                         :: "r"(dst), "l"(src + kc_ + g16 * 8) : "memory");    \
        }                                                                      \
        asm volatile("cp.async.commit_group;" ::: "memory");                   \
    } while (0)

    PREFETCH6(0);
    for (int c = 0; c < 16; c++) {
        if (c < 15) {
            PREFETCH6(c + 1);
            asm volatile("cp.async.wait_group 1;" ::: "memory");
        } else {
            asm volatile("cp.async.wait_group 0;" ::: "memory");
        }
        __syncthreads();
        uint32_t bufb = sb + (c & 1) * BUF_STRIDE;

#pragma unroll
        for (int kst = 0; kst < 2; kst++) {
            uint32_t bh[4][2];
#pragma unroll
            for (int nt = 0; nt < 4; nt++) {
                int row = wn * 32 + nt * 8 + rB;
                uint32_t off = swz64((uint32_t)(row * 64 + kst * 32 + cB));
                asm volatile(
                    "ldmatrix.sync.aligned.m8n8.x2.shared.b16 {%0,%1}, [%2];"
                    : "=r"(bh[nt][0]), "=r"(bh[nt][1])
                    : "r"(bufb + 8192 + off));
            }
#pragma unroll
            for (int mt = 0; mt < 4; mt++) {
                int row = wm * 64 + mt * 16 + rA;
                uint32_t off = swz64((uint32_t)(row * 64 + kst * 32 + cA));
                uint32_t ah[4];
                asm volatile(
                    "ldmatrix.sync.aligned.m8n8.x4.shared.b16 {%0,%1,%2,%3}, [%4];"
                    : "=r"(ah[0]), "=r"(ah[1]), "=r"(ah[2]), "=r"(ah[3])
                    : "r"(bufb + off));
#pragma unroll
                for (int nt = 0; nt < 4; nt++) {
                    asm volatile(
                        "mma.sync.aligned.m16n8k16.row.col.f32.f16.f16.f32 "
                        "{%0,%1,%2,%3}, {%4,%5,%6,%7}, {%8,%9}, {%0,%1,%2,%3};"
                        : "+f"(d[mt][nt][0]), "+f"(d[mt][nt][1]),
                          "+f"(d[mt][nt][2]), "+f"(d[mt][nt][3])
                        : "r"(ah[0]), "r"(ah[1]), "r"(ah[2]), "r"(ah[3]),
                          "r"(bh[nt][0]), "r"(bh[nt][1]));
                }
            }
        }
        __syncthreads();
    }

    int rbase = mtile + wm * 64 + (l >> 2);
    int cbase = ntile + wn * 32 + (l & 3) * 2;
#pragma unroll
    for (int nt = 0; nt < 4; nt++) {
        int col = cbase + nt * 8;
        float b0 = bias[col], b1 = bias[col + 1];
#pragma unroll
        for (int mt = 0; mt < 4; mt++) {
            int r0 = rbase + mt * 16;
            if (r0 < MROWS) {
                float2 v = make_float2(d[mt][nt][0] + b0, d[mt][nt][1] + b1);
                *(float2*)(out + (long)r0 * VOCAB + col) = v;
            }
            if (r0 + 8 < MROWS) {
                float2 v = make_float2(d[mt][nt][2] + b0, d[mt][nt][3] + b1);
                *(float2*)(out + (long)(r0 + 8) * VOCAB + col) = v;
            }
        }
    }
}

// ---------------- launch ----------------
extern "C" void kernel_launch(void* const* d_in, const int* in_sizes, int n_in,
                              void* d_out, int out_size) {
    const float* word_embs = (const float*)d_in[0];
    const float* vis       = (const float*)d_in[1];
    const float* tof       = (const float*)d_in[2];
    const float* W_map     = (const float*)d_in[4];
    const float* b_map     = (const float*)d_in[5];
    const float* w_ih      = (const float*)d_in[6];
    const float* w_hh      = (const float*)d_in[7];
    const float* b_ih      = (const float*)d_in[8];
    const float* b_hh      = (const float*)d_in[9];
    const float* W_cls     = (const float*)d_in[10];
    const float* b_cls     = (const float*)d_in[11];
    float* out = (float*)d_out;

    float *wihT, *xg, *ht;
    cudaGetSymbolAddress((void**)&wihT, g_wihT);
    cudaGetSymbolAddress((void**)&xg,   g_xg);
    cudaGetSymbolAddress((void**)&ht,   g_ht);

    cudaFuncSetAttribute(gru_persist5, cudaFuncAttributeMaxDynamicSharedMemorySize,
                         GRU_SMEM);
    cudaFuncSetAttribute(cls_mma6, cudaFuncAttributeMaxDynamicSharedMemorySize,
                         CLS_SMEM);

    // 1: fused prep (w_ih transpose + W_cls fp16 + h0 + Ah tail zero + bar reset)
    prep<<<PREP_BLOCKS, 256>>>(w_ih, W_cls, vis, tof, W_map, b_map, ht);
    // 2: x_gates
    {
        dim3 grid(G3 / 128, (MROWS + 127) / 128);
        gemm128<<<grid, 256>>>(word_embs, wihT, b_ih, xg, MROWS, G3, EMB);
    }
    // 3: persistent GRU v5
    gru_persist5<<<GRU_BLOCKS, 512, GRU_SMEM>>>(w_hh, b_hh);
    // 4: classifier
    {
        dim3 grid(MPAD / 128, VOCAB / 128);
        cls_mma6<<<grid, 256, CLS_SMEM>>>(b_cls, out);
    }
    (void)in_sizes; (void)n_in; (void)out_size;
}

// round 15
// speedup vs baseline: 1.1555x; 1.0137x over previous
#include <cuda_runtime.h>
#include <cuda_bf16.h>
#include <cuda_fp16.h>
#include <math.h>
#include <stdint.h>

typedef unsigned long long ull;

#define B_SZ   64
#define NSTEP  31
#define EMB    300
#define FEAT   4100
#define HID    512
#define G3     1536
#define VOCAB  32000
#define MROWS  1984
#define MPAD   2048
#define GRU_BLOCKS 128

// ---------------- device scratch ----------------
__device__ float g_wihT[EMB * G3];
__device__ float g_xg[MROWS * G3];
__device__ float g_ht[2][HID * B_SZ];       // transposed hidden [j][b]
__device__ __half g_Ah[MPAD * HID];         // fp16(h) rows for classifier
__device__ __half g_Bh[(long)VOCAB * HID];  // fp16(W_cls^T)
__device__ unsigned g_bar_cnt;

// ---------------- helpers ----------------
__device__ __forceinline__ void fma2(ull& d, ull a, ull b) {
    asm("fma.rn.f32x2 %0, %1, %2, %0;" : "+l"(d) : "l"(a), "l"(b));
}
__device__ __forceinline__ ull pack2(float x) {
    ull r; asm("mov.b64 %0, {%1, %2};" : "=l"(r) : "f"(x), "f"(x)); return r;
}
__device__ __forceinline__ void unpack2(ull d, float& lo, float& hi) {
    asm("mov.b64 {%0, %1}, %2;" : "=f"(lo), "=f"(hi) : "l"(d));
}
__device__ __forceinline__ uint32_t s2u(const void* p) {
    uint32_t a;
    asm("{ .reg .u64 t; cvta.to.shared.u64 t, %1; cvt.u32.u64 %0, t; }"
        : "=r"(a) : "l"(p));
    return a;
}
__device__ __forceinline__ uint32_t swz64(uint32_t bo) {
    return bo ^ (((bo >> 7) & 3) << 4);
}
__device__ __forceinline__ ulonglong2 ldcg128(const float* p) {
    ulonglong2 v;
    asm volatile("ld.global.cg.v2.u64 {%0, %1}, [%2];"
                 : "=l"(v.x), "=l"(v.y) : "l"(p));
    return v;
}

// ================= launch 1: prep1 (w_ih transpose + bar reset + Ah tail) =
#define PREP1_BLOCKS 1816
__global__ void __launch_bounds__(256)
prep1(const float* __restrict__ w_ih) {
    int blk = blockIdx.x;
    int tid = threadIdx.x;
    if (blk == 0 && tid == 0) g_bar_cnt = 0u;
    if (blk < 1800) {
        int idx = blk * 256 + tid;               // < EMB*G3 exactly
        int k = idx / G3, g = idx - k * G3;
        g_wihT[idx] = w_ih[g * EMB + k];
    } else {
        int idx = (blk - 1800) * 256 + tid;      // 4096 uint4
        uint4 z = make_uint4(0u, 0u, 0u, 0u);
        *(uint4*)(g_Ah + (long)MROWS * HID + idx * 8) = z;
    }
}

// ================= launch 2: prep2 (W_cls -> fp16 [n][k]) =================
__global__ void __launch_bounds__(256)
prep2(const float* __restrict__ W_cls) {
    __shared__ float tile[32][33];
    int cb = blockIdx.x;
    int tid = threadIdx.x;
    int n0 = (cb % 1000) * 32, k0 = (cb / 1000) * 32;
    int tx = tid & 31, ty = tid >> 5;
#pragma unroll
    for (int j = 0; j < 32; j += 8)
        tile[ty + j][tx] = W_cls[(long)(k0 + ty + j) * VOCAB + n0 + tx];
    __syncthreads();
#pragma unroll
    for (int j = 0; j < 32; j += 8) {
        int n = n0 + ty + j, k = k0 + tx;
        g_Bh[(long)n * HID + k] = __float2half_rn(tile[tx][ty + j]);
    }
}

// ================= launch 3: prep3 = h0 (transposed h[j][b]) ==============
__global__ void __launch_bounds__(256)
prep3(const float* __restrict__ vis, const float* __restrict__ tof,
      const float* __restrict__ W_map, const float* __restrict__ b_map,
      float* __restrict__ h_out) {
    __shared__ __align__(16) float fT[64][66];
    __shared__ float ws[64][8];
    __shared__ float red[4][64][8];
    int tid = threadIdx.x;
    int kg = tid >> 6;
    int inner = tid & 63;
    int bg = inner >> 3, b0 = bg * 8;
    int jl = inner & 7;
    int j0 = blockIdx.x * 8;
    int j = j0 + jl;

    ull acc[4] = {0ull, 0ull, 0ull, 0ull};
    for (int kc = 0; kc < FEAT; kc += 64) {
#pragma unroll
        for (int q = 0; q < 16; q++) {
            int id = tid + q * 256;
            int b = id >> 6, kq = id & 63;
            int f = kc + kq;
            float v = 0.f;
            if (f < 2048) v = vis[b * 2048 + f];
            else if (f < FEAT) v = tof[b * 2052 + (f - 2048)];
            fT[kq][b] = v;
        }
#pragma unroll
        for (int q = 0; q < 2; q++) {
            int id = tid + q * 256;
            int k = id >> 3, jj = id & 7;
            int f = kc + k;
            ws[k][jj] = (f < FEAT) ? W_map[f * HID + j0 + jj] : 0.f;
        }
        __syncthreads();
        int kbase = kg * 16;
#pragma unroll
        for (int i = 0; i < 16; i++) {
            int k = kbase + i;
            ull w2 = pack2(ws[k][jl]);
#pragma unroll
            for (int p = 0; p < 4; p++) {
                ull hp = *(const ull*)&fT[k][b0 + 2 * p];
                fma2(acc[p], w2, hp);
            }
        }
        __syncthreads();
    }
#pragma unroll
    for (int p = 0; p < 4; p++) {
        float lo, hi; unpack2(acc[p], lo, hi);
        red[kg][inner][2 * p] = lo; red[kg][inner][2 * p + 1] = hi;
    }
    __syncthreads();
    if (kg == 0) {
        for (int bi = 0; bi < 8; bi++) {
            int b = b0 + bi;
            float s = 0.f;
#pragma unroll
            for (int g = 0; g < 4; g++) s += red[g][inner][bi];
            s += b_map[j];
            h_out[j * B_SZ + b] = fmaxf(s, 0.f);
        }
    }
}

// ================= launch 4 (PROFILED): x_gates fp32 GEMM =================
__global__ __launch_bounds__(256)
void gemm128(const float* __restrict__ A, const float* __restrict__ Bm,
             const float* __restrict__ bias, float* __restrict__ C,
             int M, int N, int K) {
    __shared__ __align__(16) float As[16][132];
    __shared__ __align__(16) float Bs[16][128];
    int tid = threadIdx.x;
    int mtile = blockIdx.y * 128;
    int ntile = blockIdx.x * 128;
    int tm = tid >> 4, tn = tid & 15;
    int m0 = tm * 8, n0 = tn * 8;

    ull acc[8][4];
#pragma unroll
    for (int i = 0; i < 8; i++)
#pragma unroll
        for (int j = 0; j < 4; j++) acc[i][j] = 0ull;

    int nchunks = (K + 15) >> 4;
    for (int c = 0; c < nchunks; c++) {
        int kc = c << 4;
#pragma unroll
        for (int q = 0; q < 2; q++) {
            int id = tid * 2 + q;
            int row = id >> 2;
            int kq = (id & 3) * 4;
            int m = mtile + row;
            float4 v = make_float4(0.f, 0.f, 0.f, 0.f);
            if (m < M) {
                int bb = m / 31, tt = m - bb * 31;
                long roff = (long)(bb * 32 + tt) * K;
                int k = kc + kq;
                if (k + 3 < K) v = *(const float4*)(A + roff + k);
                else {
                    float tmp[4] = {0.f, 0.f, 0.f, 0.f};
#pragma unroll
                    for (int u = 0; u < 4; u++)
                        if (k + u < K) tmp[u] = A[roff + k + u];
                    v = make_float4(tmp[0], tmp[1], tmp[2], tmp[3]);
                }
            }
            As[kq + 0][row] = v.x; As[kq + 1][row] = v.y;
            As[kq + 2][row] = v.z; As[kq + 3][row] = v.w;
        }
#pragma unroll
        for (int q = 0; q < 2; q++) {
            int id = tid + q * 256;
            int r = id >> 5;
            int nq = (id & 31) * 4;
            int k = kc + r;
            float4 v = make_float4(0.f, 0.f, 0.f, 0.f);
            if (k < K) v = *(const float4*)(Bm + (long)k * N + ntile + nq);
            *(float4*)&Bs[r][nq] = v;
        }
        __syncthreads();
#pragma unroll
        for (int kk = 0; kk < 16; kk++) {
            float4 a0 = *(const float4*)&As[kk][m0];
            float4 a1 = *(const float4*)&As[kk][m0 + 4];
            const ull* bp = (const ull*)&Bs[kk][n0];
            ull b2[4] = {bp[0], bp[1], bp[2], bp[3]};
            float av[8] = {a0.x, a0.y, a0.z, a0.w, a1.x, a1.y, a1.z, a1.w};
#pragma unroll
            for (int i = 0; i < 8; i++) {
                ull ai = pack2(av[i]);
#pragma unroll
                for (int j = 0; j < 4; j++) fma2(acc[i][j], ai, b2[j]);
            }
        }
        __syncthreads();
    }
    float bvals[8];
#pragma unroll
    for (int j = 0; j < 8; j++) bvals[j] = bias[ntile + n0 + j];
#pragma unroll
    for (int i = 0; i < 8; i++) {
        int m = mtile + m0 + i;
        if (m < M) {
            float* crow = C + (long)m * N + ntile + n0;
#pragma unroll
            for (int j = 0; j < 4; j++) {
                float lo, hi; unpack2(acc[i][j], lo, hi);
                crow[2 * j]     = lo + bvals[2 * j];
                crow[2 * j + 1] = hi + bvals[2 * j + 1];
            }
        }
    }
}

// ================= launch 5: persistent GRU v5 (unchanged) ================
#define WTP 16
#define PSTR 52
#define GRU_SMEM ((HID * WTP + 32 * 16 * PSTR + 1024) * 4)

__global__ void __launch_bounds__(512)
gru_persist5(const float* __restrict__ w_hh, const float* __restrict__ b_hh) {
    extern __shared__ float sm[];
    float* w_t = sm;                         // [512][16]
    float* part = w_t + HID * WTP;           // [32 ks][16 tile][52]
    float* red2 = part + 32 * 16 * PSTR;     // [256][4]
    int tid = threadIdx.x;
    int j0 = blockIdx.x * 4;

#pragma unroll
    for (int q = 0; q < 3; q++) {
        int id = tid + q * 512;
        int r = id % 12, k4 = id / 12;
        int grow = (r >> 2) * HID + j0 + (r & 3);
        int pos = (r < 6) ? r : r + 2;
        float4 v = *(const float4*)(w_hh + (long)grow * HID + k4 * 4);
        w_t[(k4 * 4 + 0) * WTP + pos] = v.x;
        w_t[(k4 * 4 + 1) * WTP + pos] = v.y;
        w_t[(k4 * 4 + 2) * WTP + pos] = v.z;
        w_t[(k4 * 4 + 3) * WTP + pos] = v.w;
    }

    int ks = tid >> 4;
    int tile = tid & 15;
    int bg = tile >> 1, gcg = tile & 1;
    int b0 = bg * 8, gbase = gcg * 8;
    int kbase = ks * 16;
    int half = tid >> 8;
    int r2 = tid & 255;
    int b = r2 & 63, jg = r2 >> 6;
    int bgr = b >> 3, bi = b & 7;
    int tR = bgr * 2 + 0, iR = jg * 8 + bi;
    int tZ, iZ;
    if (jg < 2) { tZ = bgr * 2 + 0; iZ = (4 + jg) * 8 + bi; }
    else        { tZ = bgr * 2 + 1; iZ = (jg - 2) * 8 + bi; }
    int tN = bgr * 2 + 1, iN = (2 + jg) * 8 + bi;
    int j = j0 + jg;
    float bhr = b_hh[j], bhz = b_hh[HID + j], bhn = b_hh[2 * HID + j];
    int sbase = half * 16;
    __syncthreads();

    for (int t = 0; t < NSTEP; t++) {
        const float* h_in = g_ht[t & 1];
        float* h_out = g_ht[(t + 1) & 1];

        float xr = 0.f, xz = 0.f, xn = 0.f, hp = 0.f;
        if (half == 0) {
            const float* xrow = g_xg + ((long)b * NSTEP + t) * G3;
            xr = __ldcg(xrow + j);
            xz = __ldcg(xrow + HID + j);
            xn = __ldcg(xrow + 2 * HID + j);
            hp = __ldcg(h_in + j * B_SZ + b);
        }

        ull acc[4][6];
#pragma unroll
        for (int p = 0; p < 4; p++)
#pragma unroll
            for (int g = 0; g < 6; g++) acc[p][g] = 0ull;

#pragma unroll 8
        for (int kk = 0; kk < 16; kk++) {
            int k = kbase + kk;
            const float* hr = h_in + k * B_SZ + b0;
            ulonglong2 ha = ldcg128(hr);
            ulonglong2 hb = ldcg128(hr + 4);
            ull h2[4] = {ha.x, ha.y, hb.x, hb.y};
            float4 w0 = *(const float4*)(w_t + k * WTP + gbase);
            float4 w1 = *(const float4*)(w_t + k * WTP + gbase + 4);
            float wv[6] = {w0.x, w0.y, w0.z, w0.w, w1.x, w1.y};
#pragma unroll
            for (int g = 0; g < 6; g++) {
                ull wp = pack2(wv[g]);
#pragma unroll
                for (int p = 0; p < 4; p++) fma2(acc[p][g], wp, h2[p]);
            }
        }
        float* pb = part + (ks * 16 + tile) * PSTR;
#pragma unroll
        for (int g = 0; g < 6; g++) {
            float l0, h0v, l1, h1, l2, h2v, l3, h3;
            unpack2(acc[0][g], l0, h0v); unpack2(acc[1][g], l1, h1);
            unpack2(acc[2][g], l2, h2v); unpack2(acc[3][g], l3, h3);
            *(float4*)(pb + g * 8)     = make_float4(l0, h0v, l1, h1);
            *(float4*)(pb + g * 8 + 4) = make_float4(l2, h2v, l3, h3);
        }
        __syncthreads();

        float sr = 0.f, sz = 0.f, sn = 0.f;
#pragma unroll
        for (int si = 0; si < 16; si++) {
            int s = sbase + si;
            sr += part[(s * 16 + tR) * PSTR + iR];
            sz += part[(s * 16 + tZ) * PSTR + iZ];
            sn += part[(s * 16 + tN) * PSTR + iN];
        }
        if (half == 1) {
            red2[r2 * 4 + 0] = sr;
            red2[r2 * 4 + 1] = sz;
            red2[r2 * 4 + 2] = sn;
        }
        __syncthreads();

        if (half == 0) {
            sr += red2[r2 * 4 + 0] + bhr;
            sz += red2[r2 * 4 + 1] + bhz;
            sn += red2[r2 * 4 + 2] + bhn;
            float r_ = 1.f / (1.f + expf(-(xr + sr)));
            float z_ = 1.f / (1.f + expf(-(xz + sz)));
            float n_ = tanhf(xn + r_ * sn);
            float hn = (1.f - z_) * n_ + z_ * hp;
            h_out[j * B_SZ + b] = hn;
            g_Ah[((long)b * NSTEP + t) * HID + j] = __float2half_rn(hn);
        }

        if (t < NSTEP - 1) {
            __threadfence();
            __syncthreads();
            if (tid == 0) {
                atomicAdd(&g_bar_cnt, 1u);
                unsigned target = (unsigned)GRU_BLOCKS * (unsigned)(t + 1);
                while (*(volatile unsigned*)&g_bar_cnt < target) { }
                __threadfence();
            }
            __syncthreads();
        }
    }
}

// ================= launch 6: classifier (unchanged, 254us measured) ======
#define CLS_SMEM 32768
#define BUF_STRIDE 16384

__global__ void __launch_bounds__(256)
cls_mma6(const float* __restrict__ bias, float* __restrict__ out) {
    extern __shared__ char csm[];
    uint32_t sb = s2u(csm);
    int tid = threadIdx.x;
    int wid = tid >> 5, l = tid & 31;
    int wm = wid >> 2, wn = wid & 3;
    int mtile = blockIdx.x * 128;
    int ntile = blockIdx.y * 128;

    float d[4][4][4];
#pragma unroll
    for (int i = 0; i < 4; i++)
#pragma unroll
        for (int j = 0; j < 4; j++)
#pragma unroll
            for (int k = 0; k < 4; k++) d[i][j][k] = 0.f;

    int rA = l & 15, cA = (l >> 4) * 16;
    int rB = l & 7,  cB = ((l >> 3) & 1) * 16;

#define PREFETCH6(c)                                                           \
    do {                                                                       \
        int kc_ = (c) * 32;                                                    \
        uint32_t bufb_ = sb + ((c) & 1) * BUF_STRIDE;                          \
        _Pragma("unroll")                                                      \
        for (int q = 0; q < 4; q++) {                                          \
            int id = tid + q * 256;                                            \
            int seg = id >> 9;                                                 \
            int r = (id >> 2) & 127;                                           \
            int g16 = id & 3;                                                  \
            const __half* src = (seg == 0)                                     \
                ? g_Ah + (long)(mtile + r) * HID                               \
                : g_Bh + (long)(ntile + r) * HID;                              \
            uint32_t dst = bufb_ + seg * 8192 +                                \
                           swz64((uint32_t)(r * 64 + g16 * 16));               \
            asm volatile("cp.async.ca.shared.global [%0], [%1], 16;"           \
                         :: "r"(dst), "l"(src + kc_ + g16 * 8) : "memory");    \
        }                                                                      \
        asm volatile("cp.async.commit_group;" ::: "memory");                   \
    } while (0)

    PREFETCH6(0);
    for (int c = 0; c < 16; c++) {
        if (c < 15) {
            PREFETCH6(c + 1);
            asm volatile("cp.async.wait_group 1;" ::: "memory");
        } else {
            asm volatile("cp.async.wait_group 0;" ::: "memory");
        }
        __syncthreads();
        uint32_t bufb = sb + (c & 1) * BUF_STRIDE;

#pragma unroll
        for (int kst = 0; kst < 2; kst++) {
            uint32_t bh[4][2];
#pragma unroll
            for (int nt = 0; nt < 4; nt++) {
                int row = wn * 32 + nt * 8 + rB;
                uint32_t off = swz64((uint32_t)(row * 64 + kst * 32 + cB));
                asm volatile(
                    "ldmatrix.sync.aligned.m8n8.x2.shared.b16 {%0,%1}, [%2];"
                    : "=r"(bh[nt][0]), "=r"(bh[nt][1])
                    : "r"(bufb + 8192 + off));
            }
#pragma unroll
            for (int mt = 0; mt < 4; mt++) {
                int row = wm * 64 + mt * 16 + rA;
                uint32_t off = swz64((uint32_t)(row * 64 + kst * 32 + cA));
                uint32_t ah[4];
                asm volatile(
                    "ldmatrix.sync.aligned.m8n8.x4.shared.b16 {%0,%1,%2,%3}, [%4];"
                    : "=r"(ah[0]), "=r"(ah[1]), "=r"(ah[2]), "=r"(ah[3])
                    : "r"(bufb + off));
#pragma unroll
                for (int nt = 0; nt < 4; nt++) {
                    asm volatile(
                        "mma.sync.aligned.m16n8k16.row.col.f32.f16.f16.f32 "
                        "{%0,%1,%2,%3}, {%4,%5,%6,%7}, {%8,%9}, {%0,%1,%2,%3};"
                        : "+f"(d[mt][nt][0]), "+f"(d[mt][nt][1]),
                          "+f"(d[mt][nt][2]), "+f"(d[mt][nt][3])
                        : "r"(ah[0]), "r"(ah[1]), "r"(ah[2]), "r"(ah[3]),
                          "r"(bh[nt][0]), "r"(bh[nt][1]));
                }
            }
        }
        __syncthreads();
    }

    int rbase = mtile + wm * 64 + (l >> 2);
    int cbase = ntile + wn * 32 + (l & 3) * 2;
#pragma unroll
    for (int nt = 0; nt < 4; nt++) {
        int col = cbase + nt * 8;
        float b0 = bias[col], b1 = bias[col + 1];
#pragma unroll
        for (int mt = 0; mt < 4; mt++) {
            int r0 = rbase + mt * 16;
            if (r0 < MROWS) {
                float2 v = make_float2(d[mt][nt][0] + b0, d[mt][nt][1] + b1);
                *(float2*)(out + (long)r0 * VOCAB + col) = v;
            }
            if (r0 + 8 < MROWS) {
                float2 v = make_float2(d[mt][nt][2] + b0, d[mt][nt][3] + b1);
                *(float2*)(out + (long)(r0 + 8) * VOCAB + col) = v;
            }
        }
    }
}

// ---------------- launch ----------------
extern "C" void kernel_launch(void* const* d_in, const int* in_sizes, int n_in,
                              void* d_out, int out_size) {
    const float* word_embs = (const float*)d_in[0];
    const float* vis       = (const float*)d_in[1];
    const float* tof       = (const float*)d_in[2];
    const float* W_map     = (const float*)d_in[4];
    const float* b_map     = (const float*)d_in[5];
    const float* w_ih      = (const float*)d_in[6];
    const float* w_hh      = (const float*)d_in[7];
    const float* b_ih      = (const float*)d_in[8];
    const float* b_hh      = (const float*)d_in[9];
    const float* W_cls     = (const float*)d_in[10];
    const float* b_cls     = (const float*)d_in[11];
    float* out = (float*)d_out;

    float *wihT, *xg, *ht;
    cudaGetSymbolAddress((void**)&wihT, g_wihT);
    cudaGetSymbolAddress((void**)&xg,   g_xg);
    cudaGetSymbolAddress((void**)&ht,   g_ht);

    cudaFuncSetAttribute(gru_persist5, cudaFuncAttributeMaxDynamicSharedMemorySize,
                         GRU_SMEM);
    cudaFuncSetAttribute(cls_mma6, cudaFuncAttributeMaxDynamicSharedMemorySize,
                         CLS_SMEM);

    // 1: w_ih transpose + barrier reset + Ah tail zero
    prep1<<<PREP1_BLOCKS, 256>>>(w_ih);
    // 2: W_cls -> fp16
    prep2<<<16000, 256>>>(W_cls);
    // 3: h0
    prep3<<<64, 256>>>(vis, tof, W_map, b_map, ht);
    // 4: x_gates  <-- PROFILED SLOT
    {
        dim3 grid(G3 / 128, (MROWS + 127) / 128);
        gemm128<<<grid, 256>>>(word_embs, wihT, b_ih, xg, MROWS, G3, EMB);
    }
    // 5: persistent GRU
    gru_persist5<<<GRU_BLOCKS, 512, GRU_SMEM>>>(w_hh, b_hh);
    // 6: classifier
    {
        dim3 grid(MPAD / 128, VOCAB / 128);
        cls_mma6<<<grid, 256, CLS_SMEM>>>(b_cls, out);
    }
    (void)in_sizes; (void)n_in; (void)out_size;
}

// round 16
// speedup vs baseline: 1.1673x; 1.0102x over previous
#include <cuda_runtime.h>
#include <cuda_bf16.h>
#include <cuda_fp16.h>
#include <math.h>
#include <stdint.h>

typedef unsigned long long ull;

#define B_SZ   64
#define NSTEP  31
#define EMB    300
#define FEAT   4100
#define HID    512
#define G3     1536
#define VOCAB  32000
#define MROWS  1984
#define MPAD   2048
#define GRU_BLOCKS 128

// ---------------- device scratch ----------------
__device__ float g_wihT[EMB * G3];
__device__ float g_xg[MROWS * G3];
__device__ float g_ht[2][HID * B_SZ];       // transposed hidden [j][b]
__device__ __half g_Ah[MPAD * HID];         // fp16(h) rows for classifier
__device__ __half g_Bh[(long)VOCAB * HID];  // fp16(W_cls^T)
__device__ unsigned g_bar_cnt;

// ---------------- helpers ----------------
__device__ __forceinline__ void fma2(ull& d, ull a, ull b) {
    asm("fma.rn.f32x2 %0, %1, %2, %0;" : "+l"(d) : "l"(a), "l"(b));
}
__device__ __forceinline__ ull pack2(float x) {
    ull r; asm("mov.b64 %0, {%1, %2};" : "=l"(r) : "f"(x), "f"(x)); return r;
}
__device__ __forceinline__ void unpack2(ull d, float& lo, float& hi) {
    asm("mov.b64 {%0, %1}, %2;" : "=f"(lo), "=f"(hi) : "l"(d));
}
__device__ __forceinline__ uint32_t s2u(const void* p) {
    uint32_t a;
    asm("{ .reg .u64 t; cvta.to.shared.u64 t, %1; cvt.u32.u64 %0, t; }"
        : "=r"(a) : "l"(p));
    return a;
}
__device__ __forceinline__ uint32_t swz64(uint32_t bo) {
    return bo ^ (((bo >> 7) & 3) << 4);
}
__device__ __forceinline__ ulonglong2 ldcg128(const float* p) {
    ulonglong2 v;
    asm volatile("ld.global.cg.v2.u64 {%0, %1}, [%2];"
                 : "=l"(v.x), "=l"(v.y) : "l"(p));
    return v;
}

// ================= launch 1: prep1 (w_ih transpose + bar reset + Ah tail) =
#define PREP1_BLOCKS 1816
__global__ void __launch_bounds__(256)
prep1(const float* __restrict__ w_ih) {
    int blk = blockIdx.x;
    int tid = threadIdx.x;
    if (blk == 0 && tid == 0) g_bar_cnt = 0u;
    if (blk < 1800) {
        int idx = blk * 256 + tid;
        int k = idx / G3, g = idx - k * G3;
        g_wihT[idx] = w_ih[g * EMB + k];
    } else {
        int idx = (blk - 1800) * 256 + tid;
        uint4 z = make_uint4(0u, 0u, 0u, 0u);
        *(uint4*)(g_Ah + (long)MROWS * HID + idx * 8) = z;
    }
}

// ================= launch 2: prep23 (W_cls -> fp16, then h0) ==============
#define PREP23_BLOCKS 16064
__global__ void __launch_bounds__(256)
prep23(const float* __restrict__ W_cls,
       const float* __restrict__ vis, const float* __restrict__ tof,
       const float* __restrict__ W_map, const float* __restrict__ b_map,
       float* __restrict__ h_out) {
    __shared__ float psm[6784];
    int blk = blockIdx.x;
    int tid = threadIdx.x;

    if (blk < 16000) {
        float* tile = psm;                        // [32][33]
        int n0 = (blk % 1000) * 32, k0 = (blk / 1000) * 32;
        int tx = tid & 31, ty = tid >> 5;
#pragma unroll
        for (int j = 0; j < 32; j += 8)
            tile[(ty + j) * 33 + tx] = W_cls[(long)(k0 + ty + j) * VOCAB + n0 + tx];
        __syncthreads();
#pragma unroll
        for (int j = 0; j < 32; j += 8) {
            int n = n0 + ty + j, k = k0 + tx;
            g_Bh[(long)n * HID + k] = __float2half_rn(tile[tx * 33 + ty + j]);
        }
    } else {
        // h0: relu(concat(vis,tof) @ W_map + b_map), transposed store
        float* fT = psm;                 // [64][66]
        float* ws = fT + 64 * 66;        // [64][8]
        float* red = ws + 64 * 8;        // [4][64][8]
        int kg = tid >> 6;
        int inner = tid & 63;
        int bg = inner >> 3, b0 = bg * 8;
        int jl = inner & 7;
        int j0 = (blk - 16000) * 8;
        int j = j0 + jl;

        ull acc[4] = {0ull, 0ull, 0ull, 0ull};
        for (int kc = 0; kc < FEAT; kc += 64) {
#pragma unroll
            for (int q = 0; q < 16; q++) {
                int id = tid + q * 256;
                int b = id >> 6, kq = id & 63;
                int f = kc + kq;
                float v = 0.f;
                if (f < 2048) v = vis[b * 2048 + f];
                else if (f < FEAT) v = tof[b * 2052 + (f - 2048)];
                fT[kq * 66 + b] = v;
            }
#pragma unroll
            for (int q = 0; q < 2; q++) {
                int id = tid + q * 256;
                int k = id >> 3, jj = id & 7;
                int f = kc + k;
                ws[k * 8 + jj] = (f < FEAT) ? W_map[f * HID + j0 + jj] : 0.f;
            }
            __syncthreads();
            int kbase = kg * 16;
#pragma unroll
            for (int i = 0; i < 16; i++) {
                int k = kbase + i;
                ull w2 = pack2(ws[k * 8 + jl]);
#pragma unroll
                for (int p = 0; p < 4; p++) {
                    ull hp = *(const ull*)(fT + k * 66 + b0 + 2 * p);
                    fma2(acc[p], w2, hp);
                }
            }
            __syncthreads();
        }
#pragma unroll
        for (int p = 0; p < 4; p++) {
            float lo, hi; unpack2(acc[p], lo, hi);
            red[kg * 512 + inner * 8 + 2 * p] = lo;
            red[kg * 512 + inner * 8 + 2 * p + 1] = hi;
        }
        __syncthreads();
        if (kg == 0) {
            for (int bi = 0; bi < 8; bi++) {
                int b = b0 + bi;
                float s = 0.f;
#pragma unroll
                for (int g = 0; g < 4; g++) s += red[g * 512 + inner * 8 + bi];
                s += b_map[j];
                h_out[j * B_SZ + b] = fmaxf(s, 0.f);
            }
        }
    }
}

// ================= launch 3: x_gates fp32 GEMM =================
__global__ __launch_bounds__(256)
void gemm128(const float* __restrict__ A, const float* __restrict__ Bm,
             const float* __restrict__ bias, float* __restrict__ C,
             int M, int N, int K) {
    __shared__ __align__(16) float As[16][132];
    __shared__ __align__(16) float Bs[16][128];
    int tid = threadIdx.x;
    int mtile = blockIdx.y * 128;
    int ntile = blockIdx.x * 128;
    int tm = tid >> 4, tn = tid & 15;
    int m0 = tm * 8, n0 = tn * 8;

    ull acc[8][4];
#pragma unroll
    for (int i = 0; i < 8; i++)
#pragma unroll
        for (int j = 0; j < 4; j++) acc[i][j] = 0ull;

    int nchunks = (K + 15) >> 4;
    for (int c = 0; c < nchunks; c++) {
        int kc = c << 4;
#pragma unroll
        for (int q = 0; q < 2; q++) {
            int id = tid * 2 + q;
            int row = id >> 2;
            int kq = (id & 3) * 4;
            int m = mtile + row;
            float4 v = make_float4(0.f, 0.f, 0.f, 0.f);
            if (m < M) {
                int bb = m / 31, tt = m - bb * 31;
                long roff = (long)(bb * 32 + tt) * K;
                int k = kc + kq;
                if (k + 3 < K) v = *(const float4*)(A + roff + k);
                else {
                    float tmp[4] = {0.f, 0.f, 0.f, 0.f};
#pragma unroll
                    for (int u = 0; u < 4; u++)
                        if (k + u < K) tmp[u] = A[roff + k + u];
                    v = make_float4(tmp[0], tmp[1], tmp[2], tmp[3]);
                }
            }
            As[kq + 0][row] = v.x; As[kq + 1][row] = v.y;
            As[kq + 2][row] = v.z; As[kq + 3][row] = v.w;
        }
#pragma unroll
        for (int q = 0; q < 2; q++) {
            int id = tid + q * 256;
            int r = id >> 5;
            int nq = (id & 31) * 4;
            int k = kc + r;
            float4 v = make_float4(0.f, 0.f, 0.f, 0.f);
            if (k < K) v = *(const float4*)(Bm + (long)k * N + ntile + nq);
            *(float4*)&Bs[r][nq] = v;
        }
        __syncthreads();
#pragma unroll
        for (int kk = 0; kk < 16; kk++) {
            float4 a0 = *(const float4*)&As[kk][m0];
            float4 a1 = *(const float4*)&As[kk][m0 + 4];
            const ull* bp = (const ull*)&Bs[kk][n0];
            ull b2[4] = {bp[0], bp[1], bp[2], bp[3]};
            float av[8] = {a0.x, a0.y, a0.z, a0.w, a1.x, a1.y, a1.z, a1.w};
#pragma unroll
            for (int i = 0; i < 8; i++) {
                ull ai = pack2(av[i]);
#pragma unroll
                for (int j = 0; j < 4; j++) fma2(acc[i][j], ai, b2[j]);
            }
        }
        __syncthreads();
    }
    float bvals[8];
#pragma unroll
    for (int j = 0; j < 8; j++) bvals[j] = bias[ntile + n0 + j];
#pragma unroll
    for (int i = 0; i < 8; i++) {
        int m = mtile + m0 + i;
        if (m < M) {
            float* crow = C + (long)m * N + ntile + n0;
#pragma unroll
            for (int j = 0; j < 4; j++) {
                float lo, hi; unpack2(acc[i][j], lo, hi);
                crow[2 * j]     = lo + bvals[2 * j];
                crow[2 * j + 1] = hi + bvals[2 * j + 1];
            }
        }
    }
}

// ================= launch 4 (PROFILED): persistent GRU v6 =================
// v5 structure (512 thr, PSTR 52) with:
//  - release/acquire barrier (no threadfence, nanosleep backoff)
//  - hp carried in register (own h value)
//  - x(t+1) prefetched before the barrier
#define WTP 16
#define PSTR 52
#define GRU_SMEM ((HID * WTP + 32 * 16 * PSTR + 1024) * 4)

__global__ void __launch_bounds__(512)
gru_persist6(const float* __restrict__ w_hh, const float* __restrict__ b_hh) {
    extern __shared__ float sm[];
    float* w_t = sm;                         // [512][16]
    float* part = w_t + HID * WTP;           // [32 ks][16 tile][52]
    float* red2 = part + 32 * 16 * PSTR;     // [256][4]
    int tid = threadIdx.x;
    int j0 = blockIdx.x * 4;

#pragma unroll
    for (int q = 0; q < 3; q++) {
        int id = tid + q * 512;
        int r = id % 12, k4 = id / 12;
        int grow = (r >> 2) * HID + j0 + (r & 3);
        int pos = (r < 6) ? r : r + 2;
        float4 v = *(const float4*)(w_hh + (long)grow * HID + k4 * 4);
        w_t[(k4 * 4 + 0) * WTP + pos] = v.x;
        w_t[(k4 * 4 + 1) * WTP + pos] = v.y;
        w_t[(k4 * 4 + 2) * WTP + pos] = v.z;
        w_t[(k4 * 4 + 3) * WTP + pos] = v.w;
    }

    int ks = tid >> 4;
    int tile = tid & 15;
    int bg = tile >> 1, gcg = tile & 1;
    int b0 = bg * 8, gbase = gcg * 8;
    int kbase = ks * 16;
    int half = tid >> 8;
    int r2 = tid & 255;
    int b = r2 & 63, jg = r2 >> 6;
    int bgr = b >> 3, bi = b & 7;
    int tR = bgr * 2 + 0, iR = jg * 8 + bi;
    int tZ, iZ;
    if (jg < 2) { tZ = bgr * 2 + 0; iZ = (4 + jg) * 8 + bi; }
    else        { tZ = bgr * 2 + 1; iZ = (jg - 2) * 8 + bi; }
    int tN = bgr * 2 + 1, iN = (2 + jg) * 8 + bi;
    int j = j0 + jg;
    float bhr = b_hh[j], bhz = b_hh[HID + j], bhn = b_hh[2 * HID + j];
    int sbase = half * 16;

    // initial prefetch: x(0) and own h value
    float xr = 0.f, xz = 0.f, xn = 0.f, hp = 0.f;
    if (half == 0) {
        const float* x0 = g_xg + ((long)b * NSTEP) * G3;
        xr = __ldcg(x0 + j);
        xz = __ldcg(x0 + HID + j);
        xn = __ldcg(x0 + 2 * HID + j);
        hp = __ldcg(g_ht[0] + j * B_SZ + b);
    }
    __syncthreads();

    for (int t = 0; t < NSTEP; t++) {
        const float* h_in = g_ht[t & 1];
        float* h_out = g_ht[(t + 1) & 1];

        ull acc[4][6];
#pragma unroll
        for (int p = 0; p < 4; p++)
#pragma unroll
            for (int g = 0; g < 6; g++) acc[p][g] = 0ull;

#pragma unroll 8
        for (int kk = 0; kk < 16; kk++) {
            int k = kbase + kk;
            const float* hr = h_in + k * B_SZ + b0;
            ulonglong2 ha = ldcg128(hr);
            ulonglong2 hb = ldcg128(hr + 4);
            ull h2[4] = {ha.x, ha.y, hb.x, hb.y};
            float4 w0 = *(const float4*)(w_t + k * WTP + gbase);
            float4 w1 = *(const float4*)(w_t + k * WTP + gbase + 4);
            float wv[6] = {w0.x, w0.y, w0.z, w0.w, w1.x, w1.y};
#pragma unroll
            for (int g = 0; g < 6; g++) {
                ull wp = pack2(wv[g]);
#pragma unroll
                for (int p = 0; p < 4; p++) fma2(acc[p][g], wp, h2[p]);
            }
        }
        float* pb = part + (ks * 16 + tile) * PSTR;
#pragma unroll
        for (int g = 0; g < 6; g++) {
            float l0, h0v, l1, h1, l2, h2v, l3, h3;
            unpack2(acc[0][g], l0, h0v); unpack2(acc[1][g], l1, h1);
            unpack2(acc[2][g], l2, h2v); unpack2(acc[3][g], l3, h3);
            *(float4*)(pb + g * 8)     = make_float4(l0, h0v, l1, h1);
            *(float4*)(pb + g * 8 + 4) = make_float4(l2, h2v, l3, h3);
        }
        __syncthreads();

        float sr = 0.f, sz = 0.f, sn = 0.f;
#pragma unroll
        for (int si = 0; si < 16; si++) {
            int s = sbase + si;
            sr += part[(s * 16 + tR) * PSTR + iR];
            sz += part[(s * 16 + tZ) * PSTR + iZ];
            sn += part[(s * 16 + tN) * PSTR + iN];
        }
        if (half == 1) {
            red2[r2 * 4 + 0] = sr;
            red2[r2 * 4 + 1] = sz;
            red2[r2 * 4 + 2] = sn;
        }
        __syncthreads();

        if (half == 0) {
            sr += red2[r2 * 4 + 0] + bhr;
            sz += red2[r2 * 4 + 1] + bhz;
            sn += red2[r2 * 4 + 2] + bhn;
            float r_ = 1.f / (1.f + expf(-(xr + sr)));
            float z_ = 1.f / (1.f + expf(-(xz + sz)));
            float n_ = tanhf(xn + r_ * sn);
            float hn = (1.f - z_) * n_ + z_ * hp;
            if (t < NSTEP - 1) h_out[j * B_SZ + b] = hn;
            g_Ah[((long)b * NSTEP + t) * HID + j] = __float2half_rn(hn);
            hp = hn;                                  // own h carried in reg
            if (t < NSTEP - 1) {                      // prefetch x(t+1) now
                const float* xrow = g_xg + ((long)b * NSTEP + t + 1) * G3;
                xr = __ldcg(xrow + j);
                xz = __ldcg(xrow + HID + j);
                xn = __ldcg(xrow + 2 * HID + j);
            }
        }

        if (t < NSTEP - 1) {
            __syncthreads();            // all stores issued, intra-block HB
            if (tid == 0) {
                unsigned target = (unsigned)GRU_BLOCKS * (unsigned)(t + 1);
                asm volatile("red.release.gpu.global.add.u32 [%0], %1;"
                             :: "l"(&g_bar_cnt), "r"(1u) : "memory");
                unsigned v;
                while (1) {
                    asm volatile("ld.acquire.gpu.global.u32 %0, [%1];"
                                 : "=r"(v) : "l"(&g_bar_cnt) : "memory");
                    if (v >= target) break;
                    __nanosleep(64);
                }
            }
            __syncthreads();            // release block with acquired view
        }
    }
}

// ================= launch 5: classifier (unchanged, 254us measured) ======
#define CLS_SMEM 32768
#define BUF_STRIDE 16384

__global__ void __launch_bounds__(256)
cls_mma6(const float* __restrict__ bias, float* __restrict__ out) {
    extern __shared__ char csm[];
    uint32_t sb = s2u(csm);
    int tid = threadIdx.x;
    int wid = tid >> 5, l = tid & 31;
    int wm = wid >> 2, wn = wid & 3;
    int mtile = blockIdx.x * 128;
    int ntile = blockIdx.y * 128;

    float d[4][4][4];
#pragma unroll
    for (int i = 0; i < 4; i++)
#pragma unroll
        for (int j = 0; j < 4; j++)
#pragma unroll
            for (int k = 0; k < 4; k++) d[i][j][k] = 0.f;

    int rA = l & 15, cA = (l >> 4) * 16;
    int rB = l & 7,  cB = ((l >> 3) & 1) * 16;

#define PREFETCH6(c)                                                           \
    do {                                                                       \
        int kc_ = (c) * 32;                                                    \
        uint32_t bufb_ = sb + ((c) & 1) * BUF_STRIDE;                          \
        _Pragma("unroll")                                                      \
        for (int q = 0; q < 4; q++) {                                          \
            int id = tid + q * 256;                                            \
            int seg = id >> 9;                                                 \
            int r = (id >> 2) & 127;                                           \
            int g16 = id & 3;                                                  \
            const __half* src = (seg == 0)                                     \
                ? g_Ah + (long)(mtile + r) * HID                               \
                : g_Bh + (long)(ntile + r) * HID;                              \
            uint32_t dst = bufb_ + seg * 8192 +                                \
                           swz64((uint32_t)(r * 64 + g16 * 16));               \
            asm volatile("cp.async.ca.shared.global [%0], [%1], 16;"           \
                         :: "r"(dst), "l"(src + kc_ + g16 * 8) : "memory");    \
        }                                                                      \
        asm volatile("cp.async.commit_group;" ::: "memory");                   \
    } while (0)

    PREFETCH6(0);
    for (int c = 0; c < 16; c++) {
        if (c < 15) {
            PREFETCH6(c + 1);
            asm volatile("cp.async.wait_group 1;" ::: "memory");
        } else {
            asm volatile("cp.async.wait_group 0;" ::: "memory");
        }
        __syncthreads();
        uint32_t bufb = sb + (c & 1) * BUF_STRIDE;

#pragma unroll
        for (int kst = 0; kst < 2; kst++) {
            uint32_t bh[4][2];
#pragma unroll
            for (int nt = 0; nt < 4; nt++) {
                int row = wn * 32 + nt * 8 + rB;
                uint32_t off = swz64((uint32_t)(row * 64 + kst * 32 + cB));
                asm volatile(
                    "ldmatrix.sync.aligned.m8n8.x2.shared.b16 {%0,%1}, [%2];"
                    : "=r"(bh[nt][0]), "=r"(bh[nt][1])
                    : "r"(bufb + 8192 + off));
            }
#pragma unroll
            for (int mt = 0; mt < 4; mt++) {
                int row = wm * 64 + mt * 16 + rA;
                uint32_t off = swz64((uint32_t)(row * 64 + kst * 32 + cA));
                uint32_t ah[4];
                asm volatile(
                    "ldmatrix.sync.aligned.m8n8.x4.shared.b16 {%0,%1,%2,%3}, [%4];"
                    : "=r"(ah[0]), "=r"(ah[1]), "=r"(ah[2]), "=r"(ah[3])
                    : "r"(bufb + off));
#pragma unroll
                for (int nt = 0; nt < 4; nt++) {
                    asm volatile(
                        "mma.sync.aligned.m16n8k16.row.col.f32.f16.f16.f32 "
                        "{%0,%1,%2,%3}, {%4,%5,%6,%7}, {%8,%9}, {%0,%1,%2,%3};"
                        : "+f"(d[mt][nt][0]), "+f"(d[mt][nt][1]),
                          "+f"(d[mt][nt][2]), "+f"(d[mt][nt][3])
                        : "r"(ah[0]), "r"(ah[1]), "r"(ah[2]), "r"(ah[3]),
                          "r"(bh[nt][0]), "r"(bh[nt][1]));
                }
            }
        }
        __syncthreads();
    }

    int rbase = mtile + wm * 64 + (l >> 2);
    int cbase = ntile + wn * 32 + (l & 3) * 2;
#pragma unroll
    for (int nt = 0; nt < 4; nt++) {
        int col = cbase + nt * 8;
        float b0 = bias[col], b1 = bias[col + 1];
#pragma unroll
        for (int mt = 0; mt < 4; mt++) {
            int r0 = rbase + mt * 16;
            if (r0 < MROWS) {
                float2 v = make_float2(d[mt][nt][0] + b0, d[mt][nt][1] + b1);
                *(float2*)(out + (long)r0 * VOCAB + col) = v;
            }
            if (r0 + 8 < MROWS) {
                float2 v = make_float2(d[mt][nt][2] + b0, d[mt][nt][3] + b1);
                *(float2*)(out + (long)(r0 + 8) * VOCAB + col) = v;
            }
        }
    }
}

// ---------------- launch ----------------
extern "C" void kernel_launch(void* const* d_in, const int* in_sizes, int n_in,
                              void* d_out, int out_size) {
    const float* word_embs = (const float*)d_in[0];
    const float* vis       = (const float*)d_in[1];
    const float* tof       = (const float*)d_in[2];
    const float* W_map     = (const float*)d_in[4];
    const float* b_map     = (const float*)d_in[5];
    const float* w_ih      = (const float*)d_in[6];
    const float* w_hh      = (const float*)d_in[7];
    const float* b_ih      = (const float*)d_in[8];
    const float* b_hh      = (const float*)d_in[9];
    const float* W_cls     = (const float*)d_in[10];
    const float* b_cls     = (const float*)d_in[11];
    float* out = (float*)d_out;

    float *wihT, *xg, *ht;
    cudaGetSymbolAddress((void**)&wihT, g_wihT);
    cudaGetSymbolAddress((void**)&xg,   g_xg);
    cudaGetSymbolAddress((void**)&ht,   g_ht);

    cudaFuncSetAttribute(gru_persist6, cudaFuncAttributeMaxDynamicSharedMemorySize,
                         GRU_SMEM);
    cudaFuncSetAttribute(cls_mma6, cudaFuncAttributeMaxDynamicSharedMemorySize,
                         CLS_SMEM);

    // 1: w_ih transpose + barrier reset + Ah tail zero
    prep1<<<PREP1_BLOCKS, 256>>>(w_ih);
    // 2: W_cls -> fp16 + h0
    prep23<<<PREP23_BLOCKS, 256>>>(W_cls, vis, tof, W_map, b_map, ht);
    // 3: x_gates
    {
        dim3 grid(G3 / 128, (MROWS + 127) / 128);
        gemm128<<<grid, 256>>>(word_embs, wihT, b_ih, xg, MROWS, G3, EMB);
    }
    // 4: persistent GRU v6  <-- PROFILED SLOT
    gru_persist6<<<GRU_BLOCKS, 512, GRU_SMEM>>>(w_hh, b_hh);
    // 5: classifier
    {
        dim3 grid(MPAD / 128, VOCAB / 128);
        cls_mma6<<<grid, 256, CLS_SMEM>>>(b_cls, out);
    }
    (void)in_sizes; (void)n_in; (void)out_size;
}

// round 17
// speedup vs baseline: 1.2162x; 1.0419x over previous
#include <cuda_runtime.h>
#include <cuda_bf16.h>
#include <cuda_fp16.h>
#include <math.h>
#include <stdint.h>

typedef unsigned long long ull;

#define B_SZ   64
#define NSTEP  31
#define EMB    300
#define FEAT   4100
#define HID    512
#define G3     1536
#define VOCAB  32000
#define MROWS  1984
#define MPAD   2048
#define GRU_BLOCKS 128

// ---------------- device scratch ----------------
__device__ float g_wihT[EMB * G3];
__device__ float g_xg[MROWS * G3];
__device__ float g_ht[2][HID * B_SZ];       // transposed hidden [j][b]
__device__ __half g_Ah[MPAD * HID];         // fp16(h) rows for classifier
__device__ __half g_Bh[(long)VOCAB * HID];  // fp16(W_cls^T)
__device__ unsigned g_bar_cnt;

// ---------------- helpers ----------------
__device__ __forceinline__ void fma2(ull& d, ull a, ull b) {
    asm("fma.rn.f32x2 %0, %1, %2, %0;" : "+l"(d) : "l"(a), "l"(b));
}
__device__ __forceinline__ ull pack2(float x) {
    ull r; asm("mov.b64 %0, {%1, %2};" : "=l"(r) : "f"(x), "f"(x)); return r;
}
__device__ __forceinline__ void unpack2(ull d, float& lo, float& hi) {
    asm("mov.b64 {%0, %1}, %2;" : "=f"(lo), "=f"(hi) : "l"(d));
}
__device__ __forceinline__ uint32_t s2u(const void* p) {
    uint32_t a;
    asm("{ .reg .u64 t; cvta.to.shared.u64 t, %1; cvt.u32.u64 %0, t; }"
        : "=r"(a) : "l"(p));
    return a;
}
__device__ __forceinline__ uint32_t swz64(uint32_t bo) {
    return bo ^ (((bo >> 7) & 3) << 4);
}
__device__ __forceinline__ ulonglong2 ldcg128(const float* p) {
    ulonglong2 v;
    asm volatile("ld.global.cg.v2.u64 {%0, %1}, [%2];"
                 : "=l"(v.x), "=l"(v.y) : "l"(p));
    return v;
}

// ================= launch 1: prep1 (w_ih transpose + bar reset + Ah tail) =
#define PREP1_BLOCKS 1816
__global__ void __launch_bounds__(256)
prep1(const float* __restrict__ w_ih) {
    int blk = blockIdx.x;
    int tid = threadIdx.x;
    if (blk == 0 && tid == 0) g_bar_cnt = 0u;
    if (blk < 1800) {
        int idx = blk * 256 + tid;
        int k = idx / G3, g = idx - k * G3;
        g_wihT[idx] = w_ih[g * EMB + k];
    } else {
        int idx = (blk - 1800) * 256 + tid;
        uint4 z = make_uint4(0u, 0u, 0u, 0u);
        *(uint4*)(g_Ah + (long)MROWS * HID + idx * 8) = z;
    }
}

// ================= launch 2: prep23 (W_cls -> fp16, then h0) ==============
#define PREP23_BLOCKS 16064
__global__ void __launch_bounds__(256)
prep23(const float* __restrict__ W_cls,
       const float* __restrict__ vis, const float* __restrict__ tof,
       const float* __restrict__ W_map, const float* __restrict__ b_map,
       float* __restrict__ h_out) {
    __shared__ float psm[6784];
    int blk = blockIdx.x;
    int tid = threadIdx.x;

    if (blk < 16000) {
        float* tile = psm;                        // [32][33]
        int n0 = (blk % 1000) * 32, k0 = (blk / 1000) * 32;
        int tx = tid & 31, ty = tid >> 5;
#pragma unroll
        for (int j = 0; j < 32; j += 8)
            tile[(ty + j) * 33 + tx] = W_cls[(long)(k0 + ty + j) * VOCAB + n0 + tx];
        __syncthreads();
#pragma unroll
        for (int j = 0; j < 32; j += 8) {
            int n = n0 + ty + j, k = k0 + tx;
            g_Bh[(long)n * HID + k] = __float2half_rn(tile[tx * 33 + ty + j]);
        }
    } else {
        float* fT = psm;                 // [64][66]
        float* ws = fT + 64 * 66;        // [64][8]
        float* red = ws + 64 * 8;        // [4][64][8]
        int kg = tid >> 6;
        int inner = tid & 63;
        int bg = inner >> 3, b0 = bg * 8;
        int jl = inner & 7;
        int j0 = (blk - 16000) * 8;
        int j = j0 + jl;

        ull acc[4] = {0ull, 0ull, 0ull, 0ull};
        for (int kc = 0; kc < FEAT; kc += 64) {
#pragma unroll
            for (int q = 0; q < 16; q++) {
                int id = tid + q * 256;
                int b = id >> 6, kq = id & 63;
                int f = kc + kq;
                float v = 0.f;
                if (f < 2048) v = vis[b * 2048 + f];
                else if (f < FEAT) v = tof[b * 2052 + (f - 2048)];
                fT[kq * 66 + b] = v;
            }
#pragma unroll
            for (int q = 0; q < 2; q++) {
                int id = tid + q * 256;
                int k = id >> 3, jj = id & 7;
                int f = kc + k;
                ws[k * 8 + jj] = (f < FEAT) ? W_map[f * HID + j0 + jj] : 0.f;
            }
            __syncthreads();
            int kbase = kg * 16;
#pragma unroll
            for (int i = 0; i < 16; i++) {
                int k = kbase + i;
                ull w2 = pack2(ws[k * 8 + jl]);
#pragma unroll
                for (int p = 0; p < 4; p++) {
                    ull hp = *(const ull*)(fT + k * 66 + b0 + 2 * p);
                    fma2(acc[p], w2, hp);
                }
            }
            __syncthreads();
        }
#pragma unroll
        for (int p = 0; p < 4; p++) {
            float lo, hi; unpack2(acc[p], lo, hi);
            red[kg * 512 + inner * 8 + 2 * p] = lo;
            red[kg * 512 + inner * 8 + 2 * p + 1] = hi;
        }
        __syncthreads();
        if (kg == 0) {
            for (int bi = 0; bi < 8; bi++) {
                int b = b0 + bi;
                float s = 0.f;
#pragma unroll
                for (int g = 0; g < 4; g++) s += red[g * 512 + inner * 8 + bi];
                s += b_map[j];
                h_out[j * B_SZ + b] = fmaxf(s, 0.f);
            }
        }
    }
}

// ================= launch 3: x_gates fp32 GEMM, 64x128 tiles ==============
// grid (12, 31): 372 CTAs (1984 = 31*64 exactly). 256 thr, micro 4m x 8n.
__global__ __launch_bounds__(256)
void gemm64(const float* __restrict__ A, const float* __restrict__ Bm,
            const float* __restrict__ bias, float* __restrict__ C,
            int M, int N, int K) {
    __shared__ __align__(16) float As[16][68];
    __shared__ __align__(16) float Bs[16][128];
    int tid = threadIdx.x;
    int mtile = blockIdx.y * 64;
    int ntile = blockIdx.x * 128;
    int tm = tid >> 4, tn = tid & 15;
    int m0 = tm * 4, n0 = tn * 8;

    ull acc[4][4];
#pragma unroll
    for (int i = 0; i < 4; i++)
#pragma unroll
        for (int j = 0; j < 4; j++) acc[i][j] = 0ull;

    int nchunks = (K + 15) >> 4;
    for (int c = 0; c < nchunks; c++) {
        int kc = c << 4;
        // A tile: 64 rows x 16 k = 256 float4, 1 per thread
        {
            int row = tid >> 2;
            int kq = (tid & 3) * 4;
            int m = mtile + row;
            float4 v = make_float4(0.f, 0.f, 0.f, 0.f);
            int bb = m / 31, tt = m - bb * 31;       // word_embs row remap
            long roff = (long)(bb * 32 + tt) * K;
            int k = kc + kq;
            if (k + 3 < K) v = *(const float4*)(A + roff + k);
            else {
                float tmp[4] = {0.f, 0.f, 0.f, 0.f};
#pragma unroll
                for (int u = 0; u < 4; u++)
                    if (k + u < K) tmp[u] = A[roff + k + u];
                v = make_float4(tmp[0], tmp[1], tmp[2], tmp[3]);
            }
            As[kq + 0][row] = v.x; As[kq + 1][row] = v.y;
            As[kq + 2][row] = v.z; As[kq + 3][row] = v.w;
        }
#pragma unroll
        for (int q = 0; q < 2; q++) {
            int id = tid + q * 256;
            int r = id >> 5;
            int nq = (id & 31) * 4;
            int k = kc + r;
            float4 v = make_float4(0.f, 0.f, 0.f, 0.f);
            if (k < K) v = *(const float4*)(Bm + (long)k * N + ntile + nq);
            *(float4*)&Bs[r][nq] = v;
        }
        __syncthreads();
#pragma unroll
        for (int kk = 0; kk < 16; kk++) {
            float4 a0 = *(const float4*)&As[kk][m0];
            const ull* bp = (const ull*)&Bs[kk][n0];
            ull b2[4] = {bp[0], bp[1], bp[2], bp[3]};
            float av[4] = {a0.x, a0.y, a0.z, a0.w};
#pragma unroll
            for (int i = 0; i < 4; i++) {
                ull ai = pack2(av[i]);
#pragma unroll
                for (int j = 0; j < 4; j++) fma2(acc[i][j], ai, b2[j]);
            }
        }
        __syncthreads();
    }
    float bvals[8];
#pragma unroll
    for (int j = 0; j < 8; j++) bvals[j] = bias[ntile + n0 + j];
#pragma unroll
    for (int i = 0; i < 4; i++) {
        int m = mtile + m0 + i;
        float* crow = C + (long)m * N + ntile + n0;
#pragma unroll
        for (int j = 0; j < 4; j++) {
            float lo, hi; unpack2(acc[i][j], lo, hi);
            crow[2 * j]     = lo + bvals[2 * j];
            crow[2 * j + 1] = hi + bvals[2 * j + 1];
        }
    }
}

// ================= launch 4: persistent GRU v7 =================
// v6 + early barrier arrival (g_Ah store and x prefetch overlap the wait).
#define WTP 16
#define PSTR 52
#define GRU_SMEM ((HID * WTP + 32 * 16 * PSTR + 1024) * 4)

__global__ void __launch_bounds__(512)
gru_persist7(const float* __restrict__ w_hh, const float* __restrict__ b_hh) {
    extern __shared__ float sm[];
    float* w_t = sm;                         // [512][16]
    float* part = w_t + HID * WTP;           // [32 ks][16 tile][52]
    float* red2 = part + 32 * 16 * PSTR;     // [256][4]
    int tid = threadIdx.x;
    int j0 = blockIdx.x * 4;

#pragma unroll
    for (int q = 0; q < 3; q++) {
        int id = tid + q * 512;
        int r = id % 12, k4 = id / 12;
        int grow = (r >> 2) * HID + j0 + (r & 3);
        int pos = (r < 6) ? r : r + 2;
        float4 v = *(const float4*)(w_hh + (long)grow * HID + k4 * 4);
        w_t[(k4 * 4 + 0) * WTP + pos] = v.x;
        w_t[(k4 * 4 + 1) * WTP + pos] = v.y;
        w_t[(k4 * 4 + 2) * WTP + pos] = v.z;
        w_t[(k4 * 4 + 3) * WTP + pos] = v.w;
    }

    int ks = tid >> 4;
    int tile = tid & 15;
    int bg = tile >> 1, gcg = tile & 1;
    int b0 = bg * 8, gbase = gcg * 8;
    int kbase = ks * 16;
    int half = tid >> 8;
    int r2 = tid & 255;
    int b = r2 & 63, jg = r2 >> 6;
    int bgr = b >> 3, bi = b & 7;
    int tR = bgr * 2 + 0, iR = jg * 8 + bi;
    int tZ, iZ;
    if (jg < 2) { tZ = bgr * 2 + 0; iZ = (4 + jg) * 8 + bi; }
    else        { tZ = bgr * 2 + 1; iZ = (jg - 2) * 8 + bi; }
    int tN = bgr * 2 + 1, iN = (2 + jg) * 8 + bi;
    int j = j0 + jg;
    float bhr = b_hh[j], bhz = b_hh[HID + j], bhn = b_hh[2 * HID + j];
    int sbase = half * 16;

    float xr = 0.f, xz = 0.f, xn = 0.f, hp = 0.f;
    if (half == 0) {
        const float* x0 = g_xg + ((long)b * NSTEP) * G3;
        xr = __ldcg(x0 + j);
        xz = __ldcg(x0 + HID + j);
        xn = __ldcg(x0 + 2 * HID + j);
        hp = __ldcg(g_ht[0] + j * B_SZ + b);
    }
    __syncthreads();

    for (int t = 0; t < NSTEP; t++) {
        const float* h_in = g_ht[t & 1];
        float* h_out = g_ht[(t + 1) & 1];

        ull acc[4][6];
#pragma unroll
        for (int p = 0; p < 4; p++)
#pragma unroll
            for (int g = 0; g < 6; g++) acc[p][g] = 0ull;

#pragma unroll
        for (int kk = 0; kk < 16; kk++) {
            int k = kbase + kk;
            const float* hr = h_in + k * B_SZ + b0;
            ulonglong2 ha = ldcg128(hr);
            ulonglong2 hb = ldcg128(hr + 4);
            ull h2[4] = {ha.x, ha.y, hb.x, hb.y};
            float4 w0 = *(const float4*)(w_t + k * WTP + gbase);
            float4 w1 = *(const float4*)(w_t + k * WTP + gbase + 4);
            float wv[6] = {w0.x, w0.y, w0.z, w0.w, w1.x, w1.y};
#pragma unroll
            for (int g = 0; g < 6; g++) {
                ull wp = pack2(wv[g]);
#pragma unroll
                for (int p = 0; p < 4; p++) fma2(acc[p][g], wp, h2[p]);
            }
        }
        float* pb = part + (ks * 16 + tile) * PSTR;
#pragma unroll
        for (int g = 0; g < 6; g++) {
            float l0, h0v, l1, h1, l2, h2v, l3, h3;
            unpack2(acc[0][g], l0, h0v); unpack2(acc[1][g], l1, h1);
            unpack2(acc[2][g], l2, h2v); unpack2(acc[3][g], l3, h3);
            *(float4*)(pb + g * 8)     = make_float4(l0, h0v, l1, h1);
            *(float4*)(pb + g * 8 + 4) = make_float4(l2, h2v, l3, h3);
        }
        __syncthreads();

        float sr = 0.f, sz = 0.f, sn = 0.f;
#pragma unroll
        for (int si = 0; si < 16; si++) {
            int s = sbase + si;
            sr += part[(s * 16 + tR) * PSTR + iR];
            sz += part[(s * 16 + tZ) * PSTR + iZ];
            sn += part[(s * 16 + tN) * PSTR + iN];
        }
        if (half == 1) {
            red2[r2 * 4 + 0] = sr;
            red2[r2 * 4 + 1] = sz;
            red2[r2 * 4 + 2] = sn;
        }
        __syncthreads();

        float hn = 0.f;
        if (half == 0) {
            sr += red2[r2 * 4 + 0] + bhr;
            sz += red2[r2 * 4 + 1] + bhz;
            sn += red2[r2 * 4 + 2] + bhn;
            float r_ = 1.f / (1.f + expf(-(xr + sr)));
            float z_ = 1.f / (1.f + expf(-(xz + sz)));
            float n_ = tanhf(xn + r_ * sn);
            hn = (1.f - z_) * n_ + z_ * hp;
            if (t < NSTEP - 1) h_out[j * B_SZ + b] = hn;   // ping-pong store
            hp = hn;
        }

        if (t < NSTEP - 1) {
            __syncthreads();            // h_out stores done block-wide
            if (tid == 0) {
                asm volatile("red.release.gpu.global.add.u32 [%0], %1;"
                             :: "l"(&g_bar_cnt), "r"(1u) : "memory");
            }
            // overlap with arrival propagation: Ah store + x(t+1) prefetch
            if (half == 0) {
                g_Ah[((long)b * NSTEP + t) * HID + j] = __float2half_rn(hn);
                const float* xrow = g_xg + ((long)b * NSTEP + t + 1) * G3;
                xr = __ldcg(xrow + j);
                xz = __ldcg(xrow + HID + j);
                xn = __ldcg(xrow + 2 * HID + j);
            }
            if (tid == 0) {
                unsigned target = (unsigned)GRU_BLOCKS * (unsigned)(t + 1);
                unsigned v;
                while (1) {
                    asm volatile("ld.acquire.gpu.global.u32 %0, [%1];"
                                 : "=r"(v) : "l"(&g_bar_cnt) : "memory");
                    if (v >= target) break;
                    __nanosleep(64);
                }
            }
            __syncthreads();
        } else {
            if (half == 0)
                g_Ah[((long)b * NSTEP + t) * HID + j] = __float2half_rn(hn);
        }
    }
}

// ================= launch 5: classifier (2 CTAs/SM attempt) ===============
#define CLS_SMEM 32768
#define BUF_STRIDE 16384

__global__ void __launch_bounds__(256, 2)
cls_mma6(const float* __restrict__ bias, float* __restrict__ out) {
    extern __shared__ char csm[];
    uint32_t sb = s2u(csm);
    int tid = threadIdx.x;
    int wid = tid >> 5, l = tid & 31;
    int wm = wid >> 2, wn = wid & 3;
    int mtile = blockIdx.x * 128;
    int ntile = blockIdx.y * 128;

    float d[4][4][4];
#pragma unroll
    for (int i = 0; i < 4; i++)
#pragma unroll
        for (int j = 0; j < 4; j++)
#pragma unroll
            for (int k = 0; k < 4; k++) d[i][j][k] = 0.f;

    int rA = l & 15, cA = (l >> 4) * 16;
    int rB = l & 7,  cB = ((l >> 3) & 1) * 16;

#define PREFETCH6(c)                                                           \
    do {                                                                       \
        int kc_ = (c) * 32;                                                    \
        uint32_t bufb_ = sb + ((c) & 1) * BUF_STRIDE;                          \
        _Pragma("unroll")                                                      \
        for (int q = 0; q < 4; q++) {                                          \
            int id = tid + q * 256;                                            \
            int seg = id >> 9;                                                 \
            int r = (id >> 2) & 127;                                           \
            int g16 = id & 3;                                                  \
            const __half* src = (seg == 0)                                     \
                ? g_Ah + (long)(mtile + r) * HID                               \
                : g_Bh + (long)(ntile + r) * HID;                              \
            uint32_t dst = bufb_ + seg * 8192 +                                \
                           swz64((uint32_t)(r * 64 + g16 * 16));               \
            asm volatile("cp.async.ca.shared.global [%0], [%1], 16;"           \
                         :: "r"(dst), "l"(src + kc_ + g16 * 8) : "memory");    \
        }                                                                      \
        asm volatile("cp.async.commit_group;" ::: "memory");                   \
    } while (0)

    PREFETCH6(0);
    for (int c = 0; c < 16; c++) {
        if (c < 15) {
            PREFETCH6(c + 1);
            asm volatile("cp.async.wait_group 1;" ::: "memory");
        } else {
            asm volatile("cp.async.wait_group 0;" ::: "memory");
        }
        __syncthreads();
        uint32_t bufb = sb + (c & 1) * BUF_STRIDE;

#pragma unroll
        for (int kst = 0; kst < 2; kst++) {
            uint32_t bh[4][2];
#pragma unroll
            for (int nt = 0; nt < 4; nt++) {
                int row = wn * 32 + nt * 8 + rB;
                uint32_t off = swz64((uint32_t)(row * 64 + kst * 32 + cB));
                asm volatile(
                    "ldmatrix.sync.aligned.m8n8.x2.shared.b16 {%0,%1}, [%2];"
                    : "=r"(bh[nt][0]), "=r"(bh[nt][1])
                    : "r"(bufb + 8192 + off));
            }
#pragma unroll
            for (int mt = 0; mt < 4; mt++) {
                int row = wm * 64 + mt * 16 + rA;
                uint32_t off = swz64((uint32_t)(row * 64 + kst * 32 + cA));
                uint32_t ah[4];
                asm volatile(
                    "ldmatrix.sync.aligned.m8n8.x4.shared.b16 {%0,%1,%2,%3}, [%4];"
                    : "=r"(ah[0]), "=r"(ah[1]), "=r"(ah[2]), "=r"(ah[3])
                    : "r"(bufb + off));
#pragma unroll
                for (int nt = 0; nt < 4; nt++) {
                    asm volatile(
                        "mma.sync.aligned.m16n8k16.row.col.f32.f16.f16.f32 "
                        "{%0,%1,%2,%3}, {%4,%5,%6,%7}, {%8,%9}, {%0,%1,%2,%3};"
                        : "+f"(d[mt][nt][0]), "+f"(d[mt][nt][1]),
                          "+f"(d[mt][nt][2]), "+f"(d[mt][nt][3])
                        : "r"(ah[0]), "r"(ah[1]), "r"(ah[2]), "r"(ah[3]),
                          "r"(bh[nt][0]), "r"(bh[nt][1]));
                }
            }
        }
        __syncthreads();
    }

    int rbase = mtile + wm * 64 + (l >> 2);
    int cbase = ntile + wn * 32 + (l & 3) * 2;
#pragma unroll
    for (int nt = 0; nt < 4; nt++) {
        int col = cbase + nt * 8;
        float b0 = bias[col], b1 = bias[col + 1];
#pragma unroll
        for (int mt = 0; mt < 4; mt++) {
            int r0 = rbase + mt * 16;
            if (r0 < MROWS) {
                float2 v = make_float2(d[mt][nt][0] + b0, d[mt][nt][1] + b1);
                *(float2*)(out + (long)r0 * VOCAB + col) = v;
            }
            if (r0 + 8 < MROWS) {
                float2 v = make_float2(d[mt][nt][2] + b0, d[mt][nt][3] + b1);
                *(float2*)(out + (long)(r0 + 8) * VOCAB + col) = v;
            }
        }
    }
}

// ---------------- launch ----------------
extern "C" void kernel_launch(void* const* d_in, const int* in_sizes, int n_in,
                              void* d_out, int out_size) {
    const float* word_embs = (const float*)d_in[0];
    const float* vis       = (const float*)d_in[1];
    const float* tof       = (const float*)d_in[2];
    const float* W_map     = (const float*)d_in[4];
    const float* b_map     = (const float*)d_in[5];
    const float* w_ih      = (const float*)d_in[6];
    const float* w_hh      = (const float*)d_in[7];
    const float* b_ih      = (const float*)d_in[8];
    const float* b_hh      = (const float*)d_in[9];
    const float* W_cls     = (const float*)d_in[10];
    const float* b_cls     = (const float*)d_in[11];
    float* out = (float*)d_out;

    float *wihT, *xg, *ht;
    cudaGetSymbolAddress((void**)&wihT, g_wihT);
    cudaGetSymbolAddress((void**)&xg,   g_xg);
    cudaGetSymbolAddress((void**)&ht,   g_ht);

    cudaFuncSetAttribute(gru_persist7, cudaFuncAttributeMaxDynamicSharedMemorySize,
                         GRU_SMEM);
    cudaFuncSetAttribute(cls_mma6, cudaFuncAttributeMaxDynamicSharedMemorySize,
                         CLS_SMEM);

    // 1: w_ih transpose + barrier reset + Ah tail zero
    prep1<<<PREP1_BLOCKS, 256>>>(w_ih);
    // 2: W_cls -> fp16 + h0
    prep23<<<PREP23_BLOCKS, 256>>>(W_cls, vis, tof, W_map, b_map, ht);
    // 3: x_gates (64-row tiles, 372 CTAs)
    {
        dim3 grid(G3 / 128, MROWS / 64);
        gemm64<<<grid, 256>>>(word_embs, wihT, b_ih, xg, MROWS, G3, EMB);
    }
    // 4: persistent GRU v7
    gru_persist7<<<GRU_BLOCKS, 512, GRU_SMEM>>>(w_hh, b_hh);
    // 5: classifier (2 CTAs/SM)
    {
        dim3 grid(MPAD / 128, VOCAB / 128);
        cls_mma6<<<grid, 256, CLS_SMEM>>>(b_cls, out);
    }
    (void)in_sizes; (void)n_in; (void)out_size;
}